// round 1
// baseline (speedup 1.0000x reference)
#include <cuda_runtime.h>
#include <math.h>

// ---------------- constants ----------------
#define M_TOK 131072          // 32 * 4096 tokens
#define CDIM  256
#define NHEAD 8
#define HDIM  32
#define WSZ   8
#define NT    64              // tokens per window
#define HIDD  1024

// ---------------- device scratch (static, no allocations) ----------------
__device__ float g_bufA[M_TOK * 256];           // xw gather, then proj output
__device__ float g_attn[M_TOK * 256];           // attn output, then fc2 output
__device__ float g_x1  [M_TOK * 256];           // first residual result
__device__ float g_qkv [M_TOK * 768];           // packed qkv
__device__ float g_h   [M_TOK * 1024];          // fc1+gelu hidden
__device__ float g_bias768[768];
__device__ float g_btab[225 * 8];               // CPB bias table
__device__ float g_rpb [8 * 64 * 64];           // 16*sigmoid(rpb), per head

// ---------------- tiny precompute kernels ----------------
__global__ void pack_bias_kernel(const float* __restrict__ qb,
                                 const float* __restrict__ vb) {
    int i = threadIdx.x;            // 768 threads
    float v = 0.f;
    if (i < 256)      v = qb[i];
    else if (i >= 512) v = vb[i - 512];
    g_bias768[i] = v;
}

__global__ void __launch_bounds__(512) cpb_kernel(const float* __restrict__ w1,
                                                  const float* __restrict__ b1,
                                                  const float* __restrict__ w2) {
    int p = blockIdx.x;             // 0..224
    int i = p / 15, j = p % 15;
    float ch = (float)(i - 7), cw = (float)(j - 7);
    float t0 = ch * (8.f / 7.f), t1 = cw * (8.f / 7.f);
    // sign(t)*log2(|t|+1)/log2(8)
    t0 = copysignf(log2f(fabsf(t0) + 1.f) * (1.f / 3.f), t0);
    t1 = copysignf(log2f(fabsf(t1) + 1.f) * (1.f / 3.f), t1);

    int jt = threadIdx.x;           // 0..511 hidden units
    float hidden = fmaxf(t0 * w1[jt] + t1 * w1[512 + jt] + b1[jt], 0.f);

    __shared__ float sh[512];
    for (int h = 0; h < 8; h++) {
        sh[jt] = hidden * w2[jt * 8 + h];
        __syncthreads();
        for (int off = 256; off > 0; off >>= 1) {
            if (jt < off) sh[jt] += sh[jt + off];
            __syncthreads();
        }
        if (jt == 0) g_btab[p * 8 + h] = sh[0];
        __syncthreads();
    }
}

__global__ void rpb_kernel() {
    int n = blockIdx.x;             // query token
    int h = blockIdx.y;             // head
    int m = threadIdx.x;            // key token
    int dr = (n >> 3) - (m >> 3) + 7;
    int dc = (n & 7)  - (m & 7)  + 7;
    float v = g_btab[(dr * 15 + dc) * 8 + h];
    g_rpb[h * 4096 + n * 64 + m] = 16.f / (1.f + expf(-v));
}

// ---------------- cyclic shift + window partition gather ----------------
__global__ void gather_kernel(const float* __restrict__ x) {
    int idx = blockIdx.x * 256 + threadIdx.x;   // float4 index, M_TOK*64 total
    int row = idx >> 6;                          // window-layout token row
    int qd  = idx & 63;                          // float4 within row (256 floats)
    int b   = row >> 12;
    int rem = row & 4095;
    int win = rem >> 6;
    int n   = rem & 63;
    int hs  = (win >> 3) * 8 + (n >> 3);         // shifted-image coords
    int ws  = (win & 7)  * 8 + (n & 7);
    int hsrc = (hs + 4) & 63;                    // undo roll(-4)
    int wsrc = (ws + 4) & 63;
    int src  = b * 4096 + hsrc * 64 + wsrc;
    ((float4*)g_bufA)[(size_t)row * 64 + qd] =
        ((const float4*)x)[(size_t)src * 64 + qd];
}

// ---------------- generic fp32 GEMM: C = A(MxK) * B(KxN) + bias ----------------
// 128x64 block tile, 256 threads, 8x4 register micro-tile. M%128==0, N%64==0, K%16==0.
template <int ACT>   // 0 = none, 1 = tanh-gelu
__global__ void __launch_bounds__(256) gemm_kernel(const float* __restrict__ A,
                                                   const float* __restrict__ B,
                                                   const float* __restrict__ bias,
                                                   float* __restrict__ C,
                                                   int Mrows, int N, int K) {
    __shared__ float As[16][132];   // [k][row], padded
    __shared__ float Bs[16][68];    // [k][col], padded

    int tid = threadIdx.x;
    int tx = tid & 15, ty = tid >> 4;
    int row0 = blockIdx.y * 128;
    int col0 = blockIdx.x * 64;

    float acc[8][4];
#pragma unroll
    for (int i = 0; i < 8; i++)
#pragma unroll
        for (int j = 0; j < 4; j++) acc[i][j] = 0.f;

    int ar0 = tid >> 2;             // A row within half-tile (0..63)
    int ac0 = (tid & 3) * 4;        // A k-offset (0,4,8,12)
    int br  = tid >> 4;             // B k-row (0..15)
    int bc  = (tid & 15) * 4;       // B col (0..60)

    for (int kk = 0; kk < K; kk += 16) {
#pragma unroll
        for (int h2 = 0; h2 < 2; h2++) {
            int r = ar0 + h2 * 64;
            float4 v = *(const float4*)(A + (size_t)(row0 + r) * K + kk + ac0);
            As[ac0 + 0][r] = v.x; As[ac0 + 1][r] = v.y;
            As[ac0 + 2][r] = v.z; As[ac0 + 3][r] = v.w;
        }
        {
            float4 v = *(const float4*)(B + (size_t)(kk + br) * N + col0 + bc);
            Bs[br][bc + 0] = v.x; Bs[br][bc + 1] = v.y;
            Bs[br][bc + 2] = v.z; Bs[br][bc + 3] = v.w;
        }
        __syncthreads();
#pragma unroll
        for (int k = 0; k < 16; k++) {
            float a[8], b[4];
#pragma unroll
            for (int i = 0; i < 8; i++) a[i] = As[k][ty + 16 * i];
#pragma unroll
            for (int j = 0; j < 4; j++) b[j] = Bs[k][tx + 16 * j];
#pragma unroll
            for (int i = 0; i < 8; i++)
#pragma unroll
                for (int j = 0; j < 4; j++) acc[i][j] += a[i] * b[j];
        }
        __syncthreads();
    }

#pragma unroll
    for (int i = 0; i < 8; i++) {
        int r = row0 + ty + 16 * i;
#pragma unroll
        for (int j = 0; j < 4; j++) {
            int c = col0 + tx + 16 * j;
            float v = acc[i][j] + bias[c];
            if (ACT == 1) {
                float xx = v;
                v = 0.5f * xx * (1.f + tanhf(0.7978845608028654f *
                        (xx + 0.044715f * xx * xx * xx)));
            }
            C[(size_t)r * N + c] = v;
        }
    }
}

// ---------------- window attention: one block per (window, head) ----------------
__global__ void __launch_bounds__(64) attn_kernel(const float* __restrict__ logit_scale) {
    int bi = blockIdx.x;
    int b_ = bi >> 3;               // window index (0..2047)
    int hh = bi & 7;                // head
    int n  = threadIdx.x;           // query row (0..63)
    int win = b_ & 63;
    int wh = win >> 3, ww = win & 7;

    __shared__ float sk[64][32];
    __shared__ float sv[64][32];
    __shared__ int   sreg[64];

    const float* base = g_qkv + (size_t)(b_ * 64) * 768;

    // q row (registers), l2-normalized
    float q[32];
    {
        const float* qp = base + (size_t)n * 768 + hh * 32;
        float ss = 0.f;
#pragma unroll
        for (int d = 0; d < 32; d++) { q[d] = qp[d]; ss += q[d] * q[d]; }
        float rn = rsqrtf(fmaxf(ss, 1e-12f));
#pragma unroll
        for (int d = 0; d < 32; d++) q[d] *= rn;
    }
    // k row -> smem, l2-normalized
    {
        const float* kp = base + (size_t)n * 768 + 256 + hh * 32;
        float kr[32]; float ks = 0.f;
#pragma unroll
        for (int d = 0; d < 32; d++) { kr[d] = kp[d]; ks += kr[d] * kr[d]; }
        float rk = rsqrtf(fmaxf(ks, 1e-12f));
#pragma unroll
        for (int d = 0; d < 32; d++) sk[n][d] = kr[d] * rk;
    }
    // v row -> smem
    {
        const float* vp = base + (size_t)n * 768 + 512 + hh * 32;
#pragma unroll
        for (int d = 0; d < 32; d++) sv[n][d] = vp[d];
    }
    // shifted-window mask region id for this token
    {
        int r = n >> 3, c = n & 7;
        int habs = wh * 8 + r, wabs = ww * 8 + c;
        int rh = habs < 56 ? 0 : (habs < 60 ? 1 : 2);
        int rw = wabs < 56 ? 0 : (wabs < 60 ? 1 : 2);
        sreg[n] = rh * 3 + rw;
    }
    __syncthreads();

    float scale = expf(fminf(logit_scale[hh], 4.605170185988092f)); // ln(100)
    int myreg = sreg[n];
    const float* rpb = g_rpb + hh * 4096 + n * 64;

    float a[64];
    float amax = -1e30f;
#pragma unroll
    for (int m = 0; m < 64; m++) {
        float dot = 0.f;
#pragma unroll
        for (int d = 0; d < 32; d++) dot += q[d] * sk[m][d];
        float v = dot * scale + rpb[m];
        if (sreg[m] != myreg) v -= 100.f;
        a[m] = v;
        amax = fmaxf(amax, v);
    }
    float asum = 0.f;
#pragma unroll
    for (int m = 0; m < 64; m++) { a[m] = expf(a[m] - amax); asum += a[m]; }
    float inv = 1.f / asum;
#pragma unroll
    for (int m = 0; m < 64; m++) a[m] *= inv;

    float* op = g_attn + (size_t)(b_ * 64 + n) * 256 + hh * 32;
#pragma unroll
    for (int d = 0; d < 32; d++) {
        float s = 0.f;
#pragma unroll
        for (int m = 0; m < 64; m++) s += a[m] * sv[m][d];
        op[d] = s;
    }
}

// ---------------- LN + residual (branch 1, fuses window-reverse + unshift) ------
__global__ void __launch_bounds__(256) ln1_kernel(const float* __restrict__ x,
                                                  const float* __restrict__ scale,
                                                  const float* __restrict__ bias) {
    int warp = threadIdx.x >> 5;
    int lane = threadIdx.x & 31;
    int t = blockIdx.x * 8 + warp;          // output token (original layout)
    int b = t >> 12;
    int hw = t & 4095;
    int h = hw >> 6, w = hw & 63;
    int hs = (h + 60) & 63;                 // (h-4) mod 64
    int ws = (w + 60) & 63;
    int src = b * 4096 + ((hs >> 3) * 8 + (ws >> 3)) * 64 + ((hs & 7) * 8 + (ws & 7));

    const float* yp = g_bufA + (size_t)src * 256;   // proj output (window layout)
    float y[8]; float s = 0.f;
#pragma unroll
    for (int k = 0; k < 8; k++) { y[k] = yp[lane + 32 * k]; s += y[k]; }
#pragma unroll
    for (int o = 16; o > 0; o >>= 1) s += __shfl_xor_sync(0xffffffffu, s, o);
    float mu = s * (1.f / 256.f);
    float vs = 0.f;
#pragma unroll
    for (int k = 0; k < 8; k++) { float d = y[k] - mu; vs += d * d; }
#pragma unroll
    for (int o = 16; o > 0; o >>= 1) vs += __shfl_xor_sync(0xffffffffu, vs, o);
    float rstd = rsqrtf(vs * (1.f / 256.f) + 1e-6f);

    const float* xp = x + (size_t)t * 256;
    float* op = g_x1 + (size_t)t * 256;
#pragma unroll
    for (int k = 0; k < 8; k++) {
        int c = lane + 32 * k;
        op[c] = xp[c] + (y[k] - mu) * rstd * scale[c] + bias[c];
    }
}

// ---------------- final: out = x1 + LN(fc2_out) ----------------
__global__ void __launch_bounds__(256) final_kernel(float* __restrict__ out,
                                                    const float* __restrict__ scale,
                                                    const float* __restrict__ bias) {
    int warp = threadIdx.x >> 5;
    int lane = threadIdx.x & 31;
    int t = blockIdx.x * 8 + warp;

    const float* yp = g_attn + (size_t)t * 256;   // fc2 output
    float y[8]; float s = 0.f;
#pragma unroll
    for (int k = 0; k < 8; k++) { y[k] = yp[lane + 32 * k]; s += y[k]; }
#pragma unroll
    for (int o = 16; o > 0; o >>= 1) s += __shfl_xor_sync(0xffffffffu, s, o);
    float mu = s * (1.f / 256.f);
    float vs = 0.f;
#pragma unroll
    for (int k = 0; k < 8; k++) { float d = y[k] - mu; vs += d * d; }
#pragma unroll
    for (int o = 16; o > 0; o >>= 1) vs += __shfl_xor_sync(0xffffffffu, vs, o);
    float rstd = rsqrtf(vs * (1.f / 256.f) + 1e-6f);

    const float* x1p = g_x1 + (size_t)t * 256;
    float* op = out + (size_t)t * 256;
#pragma unroll
    for (int k = 0; k < 8; k++) {
        int c = lane + 32 * k;
        op[c] = x1p[c] + (y[k] - mu) * rstd * scale[c] + bias[c];
    }
}

// ---------------- launch ----------------
extern "C" void kernel_launch(void* const* d_in, const int* in_sizes, int n_in,
                              void* d_out, int out_size) {
    const float* x      = (const float*)d_in[0];
    const float* qkv_w  = (const float*)d_in[1];
    const float* q_bias = (const float*)d_in[2];
    const float* v_bias = (const float*)d_in[3];
    const float* lscale = (const float*)d_in[4];
    const float* cpb_w1 = (const float*)d_in[5];
    const float* cpb_b1 = (const float*)d_in[6];
    const float* cpb_w2 = (const float*)d_in[7];
    const float* proj_w = (const float*)d_in[8];
    const float* proj_b = (const float*)d_in[9];
    const float* n1s    = (const float*)d_in[10];
    const float* n1b    = (const float*)d_in[11];
    const float* n2s    = (const float*)d_in[12];
    const float* n2b    = (const float*)d_in[13];
    const float* fc1_w  = (const float*)d_in[14];
    const float* fc1_b  = (const float*)d_in[15];
    const float* fc2_w  = (const float*)d_in[16];
    const float* fc2_b  = (const float*)d_in[17];
    float* out = (float*)d_out;

    float *pA, *pAttn, *pX1, *pQkv, *pH, *pB768;
    cudaGetSymbolAddress((void**)&pA,    g_bufA);
    cudaGetSymbolAddress((void**)&pAttn, g_attn);
    cudaGetSymbolAddress((void**)&pX1,   g_x1);
    cudaGetSymbolAddress((void**)&pQkv,  g_qkv);
    cudaGetSymbolAddress((void**)&pH,    g_h);
    cudaGetSymbolAddress((void**)&pB768, g_bias768);

    pack_bias_kernel<<<1, 768>>>(q_bias, v_bias);
    cpb_kernel<<<225, 512>>>(cpb_w1, cpb_b1, cpb_w2);
    rpb_kernel<<<dim3(64, 8), 64>>>();
    gather_kernel<<<M_TOK * 64 / 256, 256>>>(x);

    // qkv: (M,256) x (256,768)
    gemm_kernel<0><<<dim3(768 / 64, M_TOK / 128), 256>>>(pA, qkv_w, pB768, pQkv,
                                                         M_TOK, 768, 256);
    attn_kernel<<<2048 * 8, 64>>>(lscale);

    // proj: (M,256) x (256,256) -> g_bufA
    gemm_kernel<0><<<dim3(256 / 64, M_TOK / 128), 256>>>(pAttn, proj_w, proj_b, pA,
                                                         M_TOK, 256, 256);
    ln1_kernel<<<M_TOK / 8, 256>>>(x, n1s, n1b);

    // fc1 + gelu: (M,256) x (256,1024) -> g_h
    gemm_kernel<1><<<dim3(1024 / 64, M_TOK / 128), 256>>>(pX1, fc1_w, fc1_b, pH,
                                                          M_TOK, 1024, 256);
    // fc2: (M,1024) x (1024,256) -> g_attn
    gemm_kernel<0><<<dim3(256 / 64, M_TOK / 128), 256>>>(pH, fc2_w, fc2_b, pAttn,
                                                         M_TOK, 256, 1024);
    final_kernel<<<M_TOK / 8, 256>>>(out, n2s, n2b);
}

// round 2
// speedup vs baseline: 1.0796x; 1.0796x over previous
#include <cuda_runtime.h>
#include <math.h>

// ---------------- constants ----------------
#define M_TOK 131072          // 32 * 4096 tokens

// ---------------- device scratch (static, no allocations) ----------------
__device__ float g_bufA[M_TOK * 256];           // xw gather, then proj output
__device__ float g_attn[M_TOK * 256];           // attn output, then fc2 output
__device__ float g_x1  [M_TOK * 256];           // first residual result
__device__ float g_qkv [M_TOK * 768];           // packed qkv
__device__ float g_h   [M_TOK * 1024];          // fc1+gelu hidden
__device__ float g_bias768[768];
__device__ float g_btab[225 * 8];               // CPB bias table
__device__ float g_rpb [8 * 64 * 64];           // 16*sigmoid(rpb), per head

// ---------------- tiny precompute kernels ----------------
__global__ void pack_bias_kernel(const float* __restrict__ qb,
                                 const float* __restrict__ vb) {
    int i = threadIdx.x;            // 768 threads
    float v = 0.f;
    if (i < 256)      v = qb[i];
    else if (i >= 512) v = vb[i - 512];
    g_bias768[i] = v;
}

__global__ void __launch_bounds__(512) cpb_kernel(const float* __restrict__ w1,
                                                  const float* __restrict__ b1,
                                                  const float* __restrict__ w2) {
    int p = blockIdx.x;             // 0..224
    int i = p / 15, j = p % 15;
    float ch = (float)(i - 7), cw = (float)(j - 7);
    float t0 = ch * (8.f / 7.f), t1 = cw * (8.f / 7.f);
    t0 = copysignf(log2f(fabsf(t0) + 1.f) * (1.f / 3.f), t0);
    t1 = copysignf(log2f(fabsf(t1) + 1.f) * (1.f / 3.f), t1);

    int jt = threadIdx.x;           // 0..511 hidden units
    float hidden = fmaxf(t0 * w1[jt] + t1 * w1[512 + jt] + b1[jt], 0.f);

    __shared__ float sh[512];
    for (int h = 0; h < 8; h++) {
        sh[jt] = hidden * w2[jt * 8 + h];
        __syncthreads();
        for (int off = 256; off > 0; off >>= 1) {
            if (jt < off) sh[jt] += sh[jt + off];
            __syncthreads();
        }
        if (jt == 0) g_btab[p * 8 + h] = sh[0];
        __syncthreads();
    }
}

__global__ void rpb_kernel() {
    int n = blockIdx.x;
    int h = blockIdx.y;
    int m = threadIdx.x;
    int dr = (n >> 3) - (m >> 3) + 7;
    int dc = (n & 7)  - (m & 7)  + 7;
    float v = g_btab[(dr * 15 + dc) * 8 + h];
    g_rpb[h * 4096 + n * 64 + m] = 16.f / (1.f + expf(-v));
}

// ---------------- cyclic shift + window partition gather ----------------
__global__ void gather_kernel(const float* __restrict__ x) {
    int idx = blockIdx.x * 256 + threadIdx.x;
    int row = idx >> 6;
    int qd  = idx & 63;
    int b   = row >> 12;
    int rem = row & 4095;
    int win = rem >> 6;
    int n   = rem & 63;
    int hs  = (win >> 3) * 8 + (n >> 3);
    int ws  = (win & 7)  * 8 + (n & 7);
    int hsrc = (hs + 4) & 63;
    int wsrc = (ws + 4) & 63;
    int src  = b * 4096 + hsrc * 64 + wsrc;
    ((float4*)g_bufA)[(size_t)row * 64 + qd] =
        ((const float4*)x)[(size_t)src * 64 + qd];
}

// ---------------- TF32 tensor-core GEMM ----------------
// C = A(MxK) * B(KxN) + bias.  BM=128, BN=128, BK=32, 256 threads (8 warps 2x4).
// Warp tile 64x32 via m16n8k8 tf32 mma. Fragments pre-permuted in smem so each
// A frag is one lds.128 and each B frag one lds.64.

__device__ __forceinline__ unsigned f2tf32(float x) {
    unsigned u;
    asm("cvt.rna.tf32.f32 %0, %1;" : "=r"(u) : "f"(x));
    return u;
}

__device__ __forceinline__ void mma_tf32(float& d0, float& d1, float& d2, float& d3,
                                         unsigned a0, unsigned a1, unsigned a2, unsigned a3,
                                         unsigned b0, unsigned b1) {
    asm volatile("mma.sync.aligned.m16n8k8.row.col.f32.tf32.tf32.f32 "
                 "{%0,%1,%2,%3}, {%4,%5,%6,%7}, {%8,%9}, {%0,%1,%2,%3};"
                 : "+f"(d0), "+f"(d1), "+f"(d2), "+f"(d3)
                 : "r"(a0), "r"(a1), "r"(a2), "r"(a3), "r"(b0), "r"(b1));
}

template <int ACT>   // 0 = none, 1 = tanh-gelu
__global__ void __launch_bounds__(256) gemm_tc(const float* __restrict__ A,
                                               const float* __restrict__ B,
                                               const float* __restrict__ bias,
                                               float* __restrict__ C,
                                               int N, int K) {
    // As: [kb(4)][mt(8)][lane(32)][reg(4)]  -> 4096 floats (tf32 bit patterns)
    // Bs: [kb(4)][nt(16)][lane(32)][reg(2)] -> 4096 floats
    __shared__ unsigned As[4096];
    __shared__ unsigned Bs[4096];

    const int tid   = threadIdx.x;
    const int warp  = tid >> 5;
    const int lane  = tid & 31;
    const int wm    = warp >> 2;          // 0..1
    const int wn    = warp & 3;           // 0..3
    const int g     = lane >> 2;          // 0..7
    const int tig   = lane & 3;           // 0..3

    const int row0 = blockIdx.y * 128;
    const int col0 = blockIdx.x * 128;

    // ---- staging addresses (A) ----
    // float4 id f = tid + 256*i : row = f>>3 (0..127), k4 = f&7
    int a_row[4], a_saddr[4];
    int b_kk[4],  b_saddr[4];
#pragma unroll
    for (int i = 0; i < 4; i++) {
        int f   = tid + 256 * i;
        int row = f >> 3, k4 = f & 7;
        a_row[i] = row;
        int mt = row >> 4, r = row & 15, gg = r & 7, hm = r >> 3;
        int kb = k4 >> 1, hk = k4 & 1;
        // element e (0..3): addr = ((kb*8+mt)*32 + gg*4 + e)*4 + hk*2+hm
        a_saddr[i] = ((kb * 8 + mt) * 32 + gg * 4) * 4 + hk * 2 + hm;

        int kk = f >> 5, c4 = f & 31;
        b_kk[i] = kk;
        int nt = c4 >> 1, gB = (c4 & 1) * 4;
        int kbB = kk >> 3, kq = kk & 7, tgB = kq & 3, hkB = kq >> 2;
        // element e: addr = ((kbB*16+nt)*32 + (gB+e)*4 + tgB)*2 + hkB
        b_saddr[i] = ((kbB * 16 + nt) * 32 + gB * 4 + tgB) * 2 + hkB;
    }

    float4 ra[4], rb[4];
    const int stages = K >> 5;

    // prefetch stage 0
#pragma unroll
    for (int i = 0; i < 4; i++) {
        int f = tid + 256 * i;
        ra[i] = *(const float4*)(A + (size_t)(row0 + a_row[i]) * K + (f & 7) * 4);
        rb[i] = *(const float4*)(B + (size_t)b_kk[i] * N + col0 + (f & 31) * 4);
    }

    float acc[4][4][4];
#pragma unroll
    for (int mt = 0; mt < 4; mt++)
#pragma unroll
        for (int nt = 0; nt < 4; nt++)
#pragma unroll
            for (int e = 0; e < 4; e++) acc[mt][nt][e] = 0.f;

    for (int s = 0; s < stages; s++) {
        // commit staged regs to smem (convert to tf32)
#pragma unroll
        for (int i = 0; i < 4; i++) {
            As[a_saddr[i] + 0]  = f2tf32(ra[i].x);
            As[a_saddr[i] + 4]  = f2tf32(ra[i].y);
            As[a_saddr[i] + 8]  = f2tf32(ra[i].z);
            As[a_saddr[i] + 12] = f2tf32(ra[i].w);
            Bs[b_saddr[i] + 0]  = f2tf32(rb[i].x);
            Bs[b_saddr[i] + 8]  = f2tf32(rb[i].y);
            Bs[b_saddr[i] + 16] = f2tf32(rb[i].z);
            Bs[b_saddr[i] + 24] = f2tf32(rb[i].w);
        }
        __syncthreads();

        // prefetch next stage
        if (s + 1 < stages) {
            const float* An = A + (s + 1) * 32;
            const float* Bn = B + (size_t)(s + 1) * 32 * N;
#pragma unroll
            for (int i = 0; i < 4; i++) {
                int f = tid + 256 * i;
                ra[i] = *(const float4*)(An + (size_t)(row0 + a_row[i]) * K + (f & 7) * 4);
                rb[i] = *(const float4*)(Bn + (size_t)b_kk[i] * N + col0 + (f & 31) * 4);
            }
        }

        // compute
#pragma unroll
        for (int kb = 0; kb < 4; kb++) {
            uint4 af[4];
            uint2 bf[4];
#pragma unroll
            for (int mtl = 0; mtl < 4; mtl++) {
                int mtg = wm * 4 + mtl;
                af[mtl] = *(const uint4*)&As[((kb * 8 + mtg) * 32 + lane) * 4];
            }
#pragma unroll
            for (int ntl = 0; ntl < 4; ntl++) {
                int ntg = wn * 4 + ntl;
                bf[ntl] = *(const uint2*)&Bs[((kb * 16 + ntg) * 32 + lane) * 2];
            }
#pragma unroll
            for (int mtl = 0; mtl < 4; mtl++)
#pragma unroll
                for (int ntl = 0; ntl < 4; ntl++)
                    mma_tf32(acc[mtl][ntl][0], acc[mtl][ntl][1],
                             acc[mtl][ntl][2], acc[mtl][ntl][3],
                             af[mtl].x, af[mtl].y, af[mtl].z, af[mtl].w,
                             bf[ntl].x, bf[ntl].y);
        }
        __syncthreads();
    }

    // epilogue
#pragma unroll
    for (int mtl = 0; mtl < 4; mtl++) {
        int r0 = row0 + wm * 64 + mtl * 16 + g;
#pragma unroll
        for (int ntl = 0; ntl < 4; ntl++) {
            int c = col0 + wn * 32 + ntl * 8 + tig * 2;
            float b0 = bias[c], b1 = bias[c + 1];
#pragma unroll
            for (int half = 0; half < 2; half++) {
                int r = r0 + half * 8;
                float v0 = acc[mtl][ntl][half * 2 + 0] + b0;
                float v1 = acc[mtl][ntl][half * 2 + 1] + b1;
                if (ACT == 1) {
                    float x0 = v0, x1 = v1;
                    v0 = 0.5f * x0 * (1.f + tanhf(0.7978845608028654f *
                            (x0 + 0.044715f * x0 * x0 * x0)));
                    v1 = 0.5f * x1 * (1.f + tanhf(0.7978845608028654f *
                            (x1 + 0.044715f * x1 * x1 * x1)));
                }
                *(float2*)(C + (size_t)r * N + c) = make_float2(v0, v1);
            }
        }
    }
}

// ---------------- window attention: one block per (window, head) ----------------
__global__ void __launch_bounds__(64) attn_kernel(const float* __restrict__ logit_scale) {
    int bi = blockIdx.x;
    int b_ = bi >> 3;
    int hh = bi & 7;
    int n  = threadIdx.x;
    int win = b_ & 63;
    int wh = win >> 3, ww = win & 7;

    __shared__ float sk[64][32];
    __shared__ float sv[64][32];
    __shared__ int   sreg[64];

    const float* base = g_qkv + (size_t)(b_ * 64) * 768;

    float q[32];
    {
        const float* qp = base + (size_t)n * 768 + hh * 32;
        float ss = 0.f;
#pragma unroll
        for (int d = 0; d < 32; d++) { q[d] = qp[d]; ss += q[d] * q[d]; }
        float rn = rsqrtf(fmaxf(ss, 1e-12f));
#pragma unroll
        for (int d = 0; d < 32; d++) q[d] *= rn;
    }
    {
        const float* kp = base + (size_t)n * 768 + 256 + hh * 32;
        float kr[32]; float ks = 0.f;
#pragma unroll
        for (int d = 0; d < 32; d++) { kr[d] = kp[d]; ks += kr[d] * kr[d]; }
        float rk = rsqrtf(fmaxf(ks, 1e-12f));
#pragma unroll
        for (int d = 0; d < 32; d++) sk[n][d] = kr[d] * rk;
    }
    {
        const float* vp = base + (size_t)n * 768 + 512 + hh * 32;
#pragma unroll
        for (int d = 0; d < 32; d++) sv[n][d] = vp[d];
    }
    {
        int r = n >> 3, c = n & 7;
        int habs = wh * 8 + r, wabs = ww * 8 + c;
        int rh = habs < 56 ? 0 : (habs < 60 ? 1 : 2);
        int rw = wabs < 56 ? 0 : (wabs < 60 ? 1 : 2);
        sreg[n] = rh * 3 + rw;
    }
    __syncthreads();

    float scale = expf(fminf(logit_scale[hh], 4.605170185988092f));
    int myreg = sreg[n];
    const float* rpb = g_rpb + hh * 4096 + n * 64;

    float a[64];
    float amax = -1e30f;
#pragma unroll
    for (int m = 0; m < 64; m++) {
        float dot = 0.f;
#pragma unroll
        for (int d = 0; d < 32; d++) dot += q[d] * sk[m][d];
        float v = dot * scale + rpb[m];
        if (sreg[m] != myreg) v -= 100.f;
        a[m] = v;
        amax = fmaxf(amax, v);
    }
    float asum = 0.f;
#pragma unroll
    for (int m = 0; m < 64; m++) { a[m] = expf(a[m] - amax); asum += a[m]; }
    float inv = 1.f / asum;
#pragma unroll
    for (int m = 0; m < 64; m++) a[m] *= inv;

    float* op = g_attn + (size_t)(b_ * 64 + n) * 256 + hh * 32;
#pragma unroll
    for (int d = 0; d < 32; d++) {
        float s = 0.f;
#pragma unroll
        for (int m = 0; m < 64; m++) s += a[m] * sv[m][d];
        op[d] = s;
    }
}

// ---------------- LN + residual (branch 1, fuses window-reverse + unshift) ------
__global__ void __launch_bounds__(256) ln1_kernel(const float* __restrict__ x,
                                                  const float* __restrict__ scale,
                                                  const float* __restrict__ bias) {
    int warp = threadIdx.x >> 5;
    int lane = threadIdx.x & 31;
    int t = blockIdx.x * 8 + warp;
    int b = t >> 12;
    int hw = t & 4095;
    int h = hw >> 6, w = hw & 63;
    int hs = (h + 60) & 63;
    int ws = (w + 60) & 63;
    int src = b * 4096 + ((hs >> 3) * 8 + (ws >> 3)) * 64 + ((hs & 7) * 8 + (ws & 7));

    const float* yp = g_bufA + (size_t)src * 256;
    float y[8]; float s = 0.f;
#pragma unroll
    for (int k = 0; k < 8; k++) { y[k] = yp[lane + 32 * k]; s += y[k]; }
#pragma unroll
    for (int o = 16; o > 0; o >>= 1) s += __shfl_xor_sync(0xffffffffu, s, o);
    float mu = s * (1.f / 256.f);
    float vs = 0.f;
#pragma unroll
    for (int k = 0; k < 8; k++) { float d = y[k] - mu; vs += d * d; }
#pragma unroll
    for (int o = 16; o > 0; o >>= 1) vs += __shfl_xor_sync(0xffffffffu, vs, o);
    float rstd = rsqrtf(vs * (1.f / 256.f) + 1e-6f);

    const float* xp = x + (size_t)t * 256;
    float* op = g_x1 + (size_t)t * 256;
#pragma unroll
    for (int k = 0; k < 8; k++) {
        int c = lane + 32 * k;
        op[c] = xp[c] + (y[k] - mu) * rstd * scale[c] + bias[c];
    }
}

// ---------------- final: out = x1 + LN(fc2_out) ----------------
__global__ void __launch_bounds__(256) final_kernel(float* __restrict__ out,
                                                    const float* __restrict__ scale,
                                                    const float* __restrict__ bias) {
    int warp = threadIdx.x >> 5;
    int lane = threadIdx.x & 31;
    int t = blockIdx.x * 8 + warp;

    const float* yp = g_attn + (size_t)t * 256;
    float y[8]; float s = 0.f;
#pragma unroll
    for (int k = 0; k < 8; k++) { y[k] = yp[lane + 32 * k]; s += y[k]; }
#pragma unroll
    for (int o = 16; o > 0; o >>= 1) s += __shfl_xor_sync(0xffffffffu, s, o);
    float mu = s * (1.f / 256.f);
    float vs = 0.f;
#pragma unroll
    for (int k = 0; k < 8; k++) { float d = y[k] - mu; vs += d * d; }
#pragma unroll
    for (int o = 16; o > 0; o >>= 1) vs += __shfl_xor_sync(0xffffffffu, vs, o);
    float rstd = rsqrtf(vs * (1.f / 256.f) + 1e-6f);

    const float* x1p = g_x1 + (size_t)t * 256;
    float* op = out + (size_t)t * 256;
#pragma unroll
    for (int k = 0; k < 8; k++) {
        int c = lane + 32 * k;
        op[c] = x1p[c] + (y[k] - mu) * rstd * scale[c] + bias[c];
    }
}

// ---------------- launch ----------------
extern "C" void kernel_launch(void* const* d_in, const int* in_sizes, int n_in,
                              void* d_out, int out_size) {
    const float* x      = (const float*)d_in[0];
    const float* qkv_w  = (const float*)d_in[1];
    const float* q_bias = (const float*)d_in[2];
    const float* v_bias = (const float*)d_in[3];
    const float* lscale = (const float*)d_in[4];
    const float* cpb_w1 = (const float*)d_in[5];
    const float* cpb_b1 = (const float*)d_in[6];
    const float* cpb_w2 = (const float*)d_in[7];
    const float* proj_w = (const float*)d_in[8];
    const float* proj_b = (const float*)d_in[9];
    const float* n1s    = (const float*)d_in[10];
    const float* n1b    = (const float*)d_in[11];
    const float* n2s    = (const float*)d_in[12];
    const float* n2b    = (const float*)d_in[13];
    const float* fc1_w  = (const float*)d_in[14];
    const float* fc1_b  = (const float*)d_in[15];
    const float* fc2_w  = (const float*)d_in[16];
    const float* fc2_b  = (const float*)d_in[17];
    float* out = (float*)d_out;

    float *pA, *pAttn, *pX1, *pQkv, *pH, *pB768;
    cudaGetSymbolAddress((void**)&pA,    g_bufA);
    cudaGetSymbolAddress((void**)&pAttn, g_attn);
    cudaGetSymbolAddress((void**)&pX1,   g_x1);
    cudaGetSymbolAddress((void**)&pQkv,  g_qkv);
    cudaGetSymbolAddress((void**)&pH,    g_h);
    cudaGetSymbolAddress((void**)&pB768, g_bias768);

    pack_bias_kernel<<<1, 768>>>(q_bias, v_bias);
    cpb_kernel<<<225, 512>>>(cpb_w1, cpb_b1, cpb_w2);
    rpb_kernel<<<dim3(64, 8), 64>>>();
    gather_kernel<<<M_TOK * 64 / 256, 256>>>(x);

    // qkv: (M,256) x (256,768)
    gemm_tc<0><<<dim3(768 / 128, M_TOK / 128), 256>>>(pA, qkv_w, pB768, pQkv, 768, 256);
    attn_kernel<<<2048 * 8, 64>>>(lscale);

    // proj: (M,256) x (256,256) -> g_bufA
    gemm_tc<0><<<dim3(256 / 128, M_TOK / 128), 256>>>(pAttn, proj_w, proj_b, pA, 256, 256);
    ln1_kernel<<<M_TOK / 8, 256>>>(x, n1s, n1b);

    // fc1 + gelu: (M,256) x (256,1024) -> g_h
    gemm_tc<1><<<dim3(1024 / 128, M_TOK / 128), 256>>>(pX1, fc1_w, fc1_b, pH, 1024, 256);
    // fc2: (M,1024) x (1024,256) -> g_attn
    gemm_tc<0><<<dim3(256 / 128, M_TOK / 128), 256>>>(pH, fc2_w, fc2_b, pAttn, 256, 1024);
    final_kernel<<<M_TOK / 8, 256>>>(out, n2s, n2b);
}

// round 5
// speedup vs baseline: 3.3553x; 3.1080x over previous
#include <cuda_runtime.h>
#include <cuda_fp16.h>
#include <math.h>
#include <stdint.h>

#define M_TOK 131072          // 32 * 4096 tokens

// ---------------- device scratch ----------------
__device__ float  g_bufA[M_TOK * 256];          // proj output (fp32)
__device__ float  g_y2  [M_TOK * 256];          // fc2 output (fp32)
__device__ float  g_x1  [M_TOK * 256];          // first residual (fp32)
__device__ float  g_qkv [M_TOK * 768];          // packed qkv (fp32)
__device__ __half g_xh  [M_TOK * 256];          // gathered x (half)  -> qkv A
__device__ __half g_ah  [M_TOK * 256];          // attn out (half)    -> proj A
__device__ __half g_x1h [M_TOK * 256];          // x1 (half)          -> fc1 A
__device__ __half g_hh  [M_TOK * 1024];         // gelu hidden (half) -> fc2 A
__device__ __half g_wTh [786432];               // transposed weights [N][K] half
__device__ float  g_bias768[768];
__device__ float  g_btab[225 * 8];
__device__ float  g_rpb [8 * 64 * 64];

#define WT_QKV  0
#define WT_PROJ 196608
#define WT_FC1  262144
#define WT_FC2  524288

// ---------------- helpers ----------------
__device__ __forceinline__ uint32_t smem_u32(const void* p) {
    uint32_t a;
    asm("{ .reg .u64 t; cvta.to.shared.u64 t, %1; cvt.u32.u64 %0, t; }"
        : "=r"(a) : "l"(p));
    return a;
}

__device__ __forceinline__ void cp16(uint32_t dst, const void* src) {
    asm volatile("cp.async.cg.shared.global [%0], [%1], 16;" :: "r"(dst), "l"(src) : "memory");
}

__device__ __forceinline__ void ldsm_x4(uint32_t& r0, uint32_t& r1, uint32_t& r2,
                                        uint32_t& r3, uint32_t addr) {
    asm volatile("ldmatrix.sync.aligned.m8n8.x4.shared.b16 {%0,%1,%2,%3}, [%4];"
                 : "=r"(r0), "=r"(r1), "=r"(r2), "=r"(r3) : "r"(addr));
}

__device__ __forceinline__ void ldsm_x2(uint32_t& r0, uint32_t& r1, uint32_t addr) {
    asm volatile("ldmatrix.sync.aligned.m8n8.x2.shared.b16 {%0,%1}, [%2];"
                 : "=r"(r0), "=r"(r1) : "r"(addr));
}

__device__ __forceinline__ void mma16816(float& d0, float& d1, float& d2, float& d3,
                                         uint32_t a0, uint32_t a1, uint32_t a2, uint32_t a3,
                                         uint32_t b0, uint32_t b1) {
    asm volatile("mma.sync.aligned.m16n8k16.row.col.f32.f16.f16.f32 "
                 "{%0,%1,%2,%3}, {%4,%5,%6,%7}, {%8,%9}, {%0,%1,%2,%3};"
                 : "+f"(d0), "+f"(d1), "+f"(d2), "+f"(d3)
                 : "r"(a0), "r"(a1), "r"(a2), "r"(a3), "r"(b0), "r"(b1));
}

#define SWZ(x) ((x) ^ (((x) >> 3) & 0x70))

__device__ __forceinline__ float gelu_f(float x) {
    float y = 0.7978845608028654f * (x + 0.044715f * x * x * x);
    float t = 1.f - 2.f / (__expf(2.f * y) + 1.f);
    return 0.5f * x * (1.f + t);
}

// ---------------- tiny precompute kernels ----------------
__global__ void pack_bias_kernel(const float* __restrict__ qb,
                                 const float* __restrict__ vb) {
    int i = threadIdx.x;
    float v = 0.f;
    if (i < 256)       v = qb[i];
    else if (i >= 512) v = vb[i - 512];
    g_bias768[i] = v;
}

__global__ void __launch_bounds__(512) cpb_kernel(const float* __restrict__ w1,
                                                  const float* __restrict__ b1,
                                                  const float* __restrict__ w2) {
    int p = blockIdx.x;
    int i = p / 15, j = p % 15;
    float t0 = (float)(i - 7) * (8.f / 7.f), t1 = (float)(j - 7) * (8.f / 7.f);
    t0 = copysignf(log2f(fabsf(t0) + 1.f) * (1.f / 3.f), t0);
    t1 = copysignf(log2f(fabsf(t1) + 1.f) * (1.f / 3.f), t1);

    int jt = threadIdx.x;
    float hidden = fmaxf(t0 * w1[jt] + t1 * w1[512 + jt] + b1[jt], 0.f);

    __shared__ float sh[512];
    for (int h = 0; h < 8; h++) {
        sh[jt] = hidden * w2[jt * 8 + h];
        __syncthreads();
        for (int off = 256; off > 0; off >>= 1) {
            if (jt < off) sh[jt] += sh[jt + off];
            __syncthreads();
        }
        if (jt == 0) g_btab[p * 8 + h] = sh[0];
        __syncthreads();
    }
}

__global__ void rpb_kernel() {
    int n = blockIdx.x, h = blockIdx.y, m = threadIdx.x;
    int dr = (n >> 3) - (m >> 3) + 7;
    int dc = (n & 7)  - (m & 7)  + 7;
    float v = g_btab[(dr * 15 + dc) * 8 + h];
    g_rpb[h * 4096 + n * 64 + m] = 16.f / (1.f + expf(-v));
}

// src[K][N] fp32 -> dst[N][K] half
__global__ void transpose_kernel(const float* __restrict__ src, __half* __restrict__ dst,
                                 int K, int N) {
    __shared__ float t[32][33];
    int kb = blockIdx.y * 32, nb = blockIdx.x * 32;
#pragma unroll
    for (int i = 0; i < 4; i++)
        t[threadIdx.y + 8 * i][threadIdx.x] =
            src[(size_t)(kb + threadIdx.y + 8 * i) * N + nb + threadIdx.x];
    __syncthreads();
#pragma unroll
    for (int i = 0; i < 4; i++)
        dst[(size_t)(nb + threadIdx.y + 8 * i) * K + kb + threadIdx.x] =
            __float2half(t[threadIdx.x][threadIdx.y + 8 * i]);
}

// ---------------- cyclic shift + window partition gather -> half ----------------
__global__ void gather_kernel(const float* __restrict__ x) {
    int idx = blockIdx.x * 256 + threadIdx.x;
    int row = idx >> 6;
    int qd  = idx & 63;
    int b   = row >> 12;
    int rem = row & 4095;
    int win = rem >> 6;
    int n   = rem & 63;
    int hs  = (win >> 3) * 8 + (n >> 3);
    int ws  = (win & 7)  * 8 + (n & 7);
    int hsrc = (hs + 4) & 63;
    int wsrc = (ws + 4) & 63;
    int src  = b * 4096 + hsrc * 64 + wsrc;
    float4 v = ((const float4*)x)[(size_t)src * 64 + qd];
    __half2 h0 = __float22half2_rn(make_float2(v.x, v.y));
    __half2 h1 = __float22half2_rn(make_float2(v.z, v.w));
    uint2 pk = make_uint2(*(uint32_t*)&h0, *(uint32_t*)&h1);
    ((uint2*)g_xh)[(size_t)row * 64 + qd] = pk;
}

// ---------------- FP16 HMMA GEMM ----------------
// Cf/Ch (M x N) = A(M x K half) * Bt(N x K half)^T + bias.
// BM=128, BN=128, BK=64 halves; 256 threads (8 warps, 2x4); warp tile 64x32.
// cp.async double-buffer -> SW128 smem -> ldmatrix -> mma.m16n8k16.
template <int ACT, int WF, int WH>
__global__ void __launch_bounds__(256) gemm_h(const __half* __restrict__ A,
                                              const __half* __restrict__ Bt,
                                              const float* __restrict__ bias,
                                              float* __restrict__ Cf,
                                              __half* __restrict__ Ch,
                                              int N, int K) {
    extern __shared__ char smem[];
    uint32_t base = (smem_u32(smem) + 1023u) & ~1023u;
    // stage s: A at base + s*32768, B at base + 16384 + s*32768
    const int tid  = threadIdx.x;
    const int warp = tid >> 5;
    const int lane = tid & 31;
    const int wm   = warp >> 2;            // 0..1
    const int wn   = warp & 3;             // 0..3
    const int row0 = blockIdx.y * 128;
    const int col0 = blockIdx.x * 128;
    const int chunks = K >> 6;

    // copy indices: idx = tid + 256*i -> row (0..127), 16B chunk c (0..7)
    const int cp_row = tid >> 3;
    const int cp_c   = tid & 7;

    float acc[4][4][4];
#pragma unroll
    for (int i = 0; i < 4; i++)
#pragma unroll
        for (int j = 0; j < 4; j++)
#pragma unroll
            for (int e = 0; e < 4; e++) acc[i][j][e] = 0.f;

    // ldmatrix base offsets (per thread)
    uint32_t a_rowbase[4], a_xmask[4];
#pragma unroll
    for (int mtl = 0; mtl < 4; mtl++) {
        int r = wm * 64 + mtl * 16 + (lane & 15);
        a_rowbase[mtl] = r * 128 + ((lane >> 4) * 16);
        a_xmask[mtl]   = (r & 7) * 16;
    }
    uint32_t b_rowbase[4], b_xmask[4];
#pragma unroll
    for (int ntl = 0; ntl < 4; ntl++) {
        int r = wn * 32 + ntl * 8 + (lane & 7);
        b_rowbase[ntl] = r * 128 + (((lane >> 3) & 1) * 16);
        b_xmask[ntl]   = (r & 7) * 16;
    }

    // prefetch chunk 0 into stage 0
    {
        uint32_t aB = base, bB = base + 16384u;
#pragma unroll
        for (int i = 0; i < 4; i++) {
            int row = cp_row + i * 32;
            cp16(aB + SWZ(row * 128 + cp_c * 16), A  + (size_t)(row0 + row) * K + cp_c * 8);
            cp16(bB + SWZ(row * 128 + cp_c * 16), Bt + (size_t)(col0 + row) * K + cp_c * 8);
        }
        asm volatile("cp.async.commit_group;" ::: "memory");
    }

    for (int c = 0; c < chunks; c++) {
        if (c + 1 < chunks) {
            uint32_t st = ((c + 1) & 1) * 32768u;
            uint32_t aB = base + st, bB = base + 16384u + st;
            int kk = (c + 1) * 64;
#pragma unroll
            for (int i = 0; i < 4; i++) {
                int row = cp_row + i * 32;
                cp16(aB + SWZ(row * 128 + cp_c * 16),
                     A  + (size_t)(row0 + row) * K + kk + cp_c * 8);
                cp16(bB + SWZ(row * 128 + cp_c * 16),
                     Bt + (size_t)(col0 + row) * K + kk + cp_c * 8);
            }
            asm volatile("cp.async.commit_group;" ::: "memory");
            asm volatile("cp.async.wait_group 1;" ::: "memory");
        } else {
            asm volatile("cp.async.wait_group 0;" ::: "memory");
        }
        __syncthreads();

        uint32_t st = (c & 1) * 32768u;
        uint32_t aCur = base + st, bCur = base + 16384u + st;
#pragma unroll
        for (int ks = 0; ks < 4; ks++) {
            uint32_t af[4][4];
            uint32_t bf[4][2];
            uint32_t ko = ks << 5;
#pragma unroll
            for (int mtl = 0; mtl < 4; mtl++)
                ldsm_x4(af[mtl][0], af[mtl][1], af[mtl][2], af[mtl][3],
                        aCur + (a_rowbase[mtl] ^ a_xmask[mtl] ^ (ko ^ ((ko & 0x70) ))) // placeholder
                        );
            // NOTE: ko only touches bits 5-6 which are inside the XOR field; compute directly:
#pragma unroll
            for (int mtl = 0; mtl < 4; mtl++) {
                uint32_t off = (a_rowbase[mtl] + ko);
                (void)off;
            }
#pragma unroll
            for (int ntl = 0; ntl < 4; ntl++)
                ldsm_x2(bf[ntl][0], bf[ntl][1],
                        bCur + ((b_rowbase[ntl] + ko) ^ b_xmask[ntl]));
            // redo A loads correctly (overwrites placeholder loads)
#pragma unroll
            for (int mtl = 0; mtl < 4; mtl++)
                ldsm_x4(af[mtl][0], af[mtl][1], af[mtl][2], af[mtl][3],
                        aCur + ((a_rowbase[mtl] + ko) ^ a_xmask[mtl]));
#pragma unroll
            for (int mtl = 0; mtl < 4; mtl++)
#pragma unroll
                for (int ntl = 0; ntl < 4; ntl++)
                    mma16816(acc[mtl][ntl][0], acc[mtl][ntl][1],
                             acc[mtl][ntl][2], acc[mtl][ntl][3],
                             af[mtl][0], af[mtl][1], af[mtl][2], af[mtl][3],
                             bf[ntl][0], bf[ntl][1]);
        }
        __syncthreads();
    }

    // epilogue: d0,d1 at (r, c),(r,c+1); d2,d3 at (r+8, ...)
#pragma unroll
    for (int mtl = 0; mtl < 4; mtl++) {
        int rbase = row0 + wm * 64 + mtl * 16 + (lane >> 2);
#pragma unroll
        for (int ntl = 0; ntl < 4; ntl++) {
            int cc = col0 + wn * 32 + ntl * 8 + (lane & 3) * 2;
            float b0 = bias[cc], b1 = bias[cc + 1];
#pragma unroll
            for (int half = 0; half < 2; half++) {
                int r = rbase + half * 8;
                float v0 = acc[mtl][ntl][half * 2 + 0] + b0;
                float v1 = acc[mtl][ntl][half * 2 + 1] + b1;
                if (ACT == 1) { v0 = gelu_f(v0); v1 = gelu_f(v1); }
                if (WF)
                    *(float2*)(Cf + (size_t)r * N + cc) = make_float2(v0, v1);
                if (WH) {
                    __half2 hv = __float22half2_rn(make_float2(v0, v1));
                    *(uint32_t*)(Ch + (size_t)r * N + cc) = *(uint32_t*)&hv;
                }
            }
        }
    }
}

// ---------------- window attention ----------------
__global__ void __launch_bounds__(64) attn_kernel(const float* __restrict__ logit_scale) {
    int bi = blockIdx.x;
    int b_ = bi >> 3;
    int hh = bi & 7;
    int n  = threadIdx.x;
    int win = b_ & 63;
    int wh = win >> 3, ww = win & 7;

    __shared__ float4 sk4[64][8];
    __shared__ float4 sv4[64][8];
    __shared__ int    sreg[64];

    const float* base = g_qkv + (size_t)(b_ * 64) * 768;

    float4 q4[8];
    {
        const float4* qp = (const float4*)(base + (size_t)n * 768 + hh * 32);
        float ss = 0.f;
#pragma unroll
        for (int j = 0; j < 8; j++) {
            q4[j] = qp[j];
            ss += q4[j].x * q4[j].x + q4[j].y * q4[j].y +
                  q4[j].z * q4[j].z + q4[j].w * q4[j].w;
        }
        float rn = rsqrtf(fmaxf(ss, 1e-12f));
#pragma unroll
        for (int j = 0; j < 8; j++) {
            q4[j].x *= rn; q4[j].y *= rn; q4[j].z *= rn; q4[j].w *= rn;
        }
    }
    {
        const float4* kp = (const float4*)(base + (size_t)n * 768 + 256 + hh * 32);
        float4 kr[8]; float ks = 0.f;
#pragma unroll
        for (int j = 0; j < 8; j++) {
            kr[j] = kp[j];
            ks += kr[j].x * kr[j].x + kr[j].y * kr[j].y +
                  kr[j].z * kr[j].z + kr[j].w * kr[j].w;
        }
        float rk = rsqrtf(fmaxf(ks, 1e-12f));
#pragma unroll
        for (int j = 0; j < 8; j++) {
            kr[j].x *= rk; kr[j].y *= rk; kr[j].z *= rk; kr[j].w *= rk;
            sk4[n][j] = kr[j];
        }
    }
    {
        const float4* vp = (const float4*)(base + (size_t)n * 768 + 512 + hh * 32);
#pragma unroll
        for (int j = 0; j < 8; j++) sv4[n][j] = vp[j];
    }
    {
        int r = n >> 3, c = n & 7;
        int habs = wh * 8 + r, wabs = ww * 8 + c;
        int rh = habs < 56 ? 0 : (habs < 60 ? 1 : 2);
        int rw = wabs < 56 ? 0 : (wabs < 60 ? 1 : 2);
        sreg[n] = rh * 3 + rw;
    }
    __syncthreads();

    float scale = __expf(fminf(logit_scale[hh], 4.605170185988092f));
    int myreg = sreg[n];
    const float* rpb = g_rpb + hh * 4096 + n * 64;

    float a[64];
    float amax = -1e30f;
#pragma unroll
    for (int m = 0; m < 64; m++) {
        float dot = 0.f;
#pragma unroll
        for (int j = 0; j < 8; j++) {
            float4 kk = sk4[m][j];
            dot += q4[j].x * kk.x + q4[j].y * kk.y + q4[j].z * kk.z + q4[j].w * kk.w;
        }
        float v = dot * scale + rpb[m];
        if (sreg[m] != myreg) v -= 100.f;
        a[m] = v;
        amax = fmaxf(amax, v);
    }
    float asum = 0.f;
#pragma unroll
    for (int m = 0; m < 64; m++) { a[m] = __expf(a[m] - amax); asum += a[m]; }
    float inv = 1.f / asum;

    float4 o[8];
#pragma unroll
    for (int j = 0; j < 8; j++) o[j] = make_float4(0.f, 0.f, 0.f, 0.f);
#pragma unroll
    for (int m = 0; m < 64; m++) {
        float am = a[m] * inv;
#pragma unroll
        for (int j = 0; j < 8; j++) {
            float4 vv = sv4[m][j];
            o[j].x += am * vv.x; o[j].y += am * vv.y;
            o[j].z += am * vv.z; o[j].w += am * vv.w;
        }
    }
    // write half (proj GEMM input)
    uint2* op = (uint2*)(g_ah + (size_t)(b_ * 64 + n) * 256 + hh * 32);
#pragma unroll
    for (int j = 0; j < 8; j++) {
        __half2 h0 = __float22half2_rn(make_float2(o[j].x, o[j].y));
        __half2 h1 = __float22half2_rn(make_float2(o[j].z, o[j].w));
        op[j] = make_uint2(*(uint32_t*)&h0, *(uint32_t*)&h1);
    }
}

// ---------------- LN + residual (branch 1, fuses window-reverse + unshift) ------
__global__ void __launch_bounds__(256) ln1_kernel(const float* __restrict__ x,
                                                  const float* __restrict__ scale,
                                                  const float* __restrict__ bias) {
    int warp = threadIdx.x >> 5;
    int lane = threadIdx.x & 31;
    int t = blockIdx.x * 8 + warp;
    int b = t >> 12;
    int hw = t & 4095;
    int h = hw >> 6, w = hw & 63;
    int hs = (h + 60) & 63;
    int ws = (w + 60) & 63;
    int src = b * 4096 + ((hs >> 3) * 8 + (ws >> 3)) * 64 + ((hs & 7) * 8 + (ws & 7));

    const float* yp = g_bufA + (size_t)src * 256;
    float y[8]; float s = 0.f;
#pragma unroll
    for (int k = 0; k < 8; k++) { y[k] = yp[lane + 32 * k]; s += y[k]; }
#pragma unroll
    for (int o = 16; o > 0; o >>= 1) s += __shfl_xor_sync(0xffffffffu, s, o);
    float mu = s * (1.f / 256.f);
    float vs = 0.f;
#pragma unroll
    for (int k = 0; k < 8; k++) { float d = y[k] - mu; vs += d * d; }
#pragma unroll
    for (int o = 16; o > 0; o >>= 1) vs += __shfl_xor_sync(0xffffffffu, vs, o);
    float rstd = rsqrtf(vs * (1.f / 256.f) + 1e-6f);

    const float* xp = x + (size_t)t * 256;
    float*  op  = g_x1  + (size_t)t * 256;
    __half* oph = g_x1h + (size_t)t * 256;
#pragma unroll
    for (int k = 0; k < 8; k++) {
        int c = lane + 32 * k;
        float v = xp[c] + (y[k] - mu) * rstd * scale[c] + bias[c];
        op[c]  = v;
        oph[c] = __float2half(v);
    }
}

// ---------------- final: out = x1 + LN(fc2_out) ----------------
__global__ void __launch_bounds__(256) final_kernel(float* __restrict__ out,
                                                    const float* __restrict__ scale,
                                                    const float* __restrict__ bias) {
    int warp = threadIdx.x >> 5;
    int lane = threadIdx.x & 31;
    int t = blockIdx.x * 8 + warp;

    const float* yp = g_y2 + (size_t)t * 256;
    float y[8]; float s = 0.f;
#pragma unroll
    for (int k = 0; k < 8; k++) { y[k] = yp[lane + 32 * k]; s += y[k]; }
#pragma unroll
    for (int o = 16; o > 0; o >>= 1) s += __shfl_xor_sync(0xffffffffu, s, o);
    float mu = s * (1.f / 256.f);
    float vs = 0.f;
#pragma unroll
    for (int k = 0; k < 8; k++) { float d = y[k] - mu; vs += d * d; }
#pragma unroll
    for (int o = 16; o > 0; o >>= 1) vs += __shfl_xor_sync(0xffffffffu, vs, o);
    float rstd = rsqrtf(vs * (1.f / 256.f) + 1e-6f);

    const float* x1p = g_x1 + (size_t)t * 256;
    float* op = out + (size_t)t * 256;
#pragma unroll
    for (int k = 0; k < 8; k++) {
        int c = lane + 32 * k;
        op[c] = x1p[c] + (y[k] - mu) * rstd * scale[c] + bias[c];
    }
}

// ---------------- launch ----------------
#define GEMM_SMEM (65536 + 1024)

extern "C" void kernel_launch(void* const* d_in, const int* in_sizes, int n_in,
                              void* d_out, int out_size) {
    const float* x      = (const float*)d_in[0];
    const float* qkv_w  = (const float*)d_in[1];
    const float* q_bias = (const float*)d_in[2];
    const float* v_bias = (const float*)d_in[3];
    const float* lscale = (const float*)d_in[4];
    const float* cpb_w1 = (const float*)d_in[5];
    const float* cpb_b1 = (const float*)d_in[6];
    const float* cpb_w2 = (const float*)d_in[7];
    const float* proj_w = (const float*)d_in[8];
    const float* proj_b = (const float*)d_in[9];
    const float* n1s    = (const float*)d_in[10];
    const float* n1b    = (const float*)d_in[11];
    const float* n2s    = (const float*)d_in[12];
    const float* n2b    = (const float*)d_in[13];
    const float* fc1_w  = (const float*)d_in[14];
    const float* fc1_b  = (const float*)d_in[15];
    const float* fc2_w  = (const float*)d_in[16];
    const float* fc2_b  = (const float*)d_in[17];
    float* out = (float*)d_out;

    float *pA, *pY2, *pQkv, *pB768;
    __half *pXh, *pAh, *pX1h, *pHh, *pWTh;
    cudaGetSymbolAddress((void**)&pA,    g_bufA);
    cudaGetSymbolAddress((void**)&pY2,   g_y2);
    cudaGetSymbolAddress((void**)&pQkv,  g_qkv);
    cudaGetSymbolAddress((void**)&pB768, g_bias768);
    cudaGetSymbolAddress((void**)&pXh,   g_xh);
    cudaGetSymbolAddress((void**)&pAh,   g_ah);
    cudaGetSymbolAddress((void**)&pX1h,  g_x1h);
    cudaGetSymbolAddress((void**)&pHh,   g_hh);
    cudaGetSymbolAddress((void**)&pWTh,  g_wTh);

    cudaFuncSetAttribute(gemm_h<0,1,0>, cudaFuncAttributeMaxDynamicSharedMemorySize, GEMM_SMEM);
    cudaFuncSetAttribute(gemm_h<1,0,1>, cudaFuncAttributeMaxDynamicSharedMemorySize, GEMM_SMEM);

    pack_bias_kernel<<<1, 768>>>(q_bias, v_bias);
    cpb_kernel<<<225, 512>>>(cpb_w1, cpb_b1, cpb_w2);
    rpb_kernel<<<dim3(64, 8), 64>>>();

    transpose_kernel<<<dim3(768 / 32, 256 / 32),  dim3(32, 8)>>>(qkv_w,  pWTh + WT_QKV,  256, 768);
    transpose_kernel<<<dim3(256 / 32, 256 / 32),  dim3(32, 8)>>>(proj_w, pWTh + WT_PROJ, 256, 256);
    transpose_kernel<<<dim3(1024 / 32, 256 / 32), dim3(32, 8)>>>(fc1_w,  pWTh + WT_FC1,  256, 1024);
    transpose_kernel<<<dim3(256 / 32, 1024 / 32), dim3(32, 8)>>>(fc2_w,  pWTh + WT_FC2,  1024, 256);

    gather_kernel<<<M_TOK * 64 / 256, 256>>>(x);

    // qkv: (M,256)x(256,768) fp16 -> fp32
    gemm_h<0,1,0><<<dim3(6, M_TOK / 128), 256, GEMM_SMEM>>>(
        pXh, pWTh + WT_QKV, pB768, pQkv, (__half*)0, 768, 256);
    attn_kernel<<<2048 * 8, 64>>>(lscale);

    // proj: (M,256)x(256,256) -> fp32 g_bufA
    gemm_h<0,1,0><<<dim3(2, M_TOK / 128), 256, GEMM_SMEM>>>(
        pAh, pWTh + WT_PROJ, proj_b, pA, (__half*)0, 256, 256);
    ln1_kernel<<<M_TOK / 8, 256>>>(x, n1s, n1b);

    // fc1+gelu: (M,256)x(256,1024) -> half g_hh
    gemm_h<1,0,1><<<dim3(8, M_TOK / 128), 256, GEMM_SMEM>>>(
        pX1h, pWTh + WT_FC1, fc1_b, (float*)0, pHh, 1024, 256);
    // fc2: (M,1024)x(1024,256) -> fp32 g_y2
    gemm_h<0,1,0><<<dim3(2, M_TOK / 128), 256, GEMM_SMEM>>>(
        pHh, pWTh + WT_FC2, fc2_b, pY2, (__half*)0, 256, 1024);
    final_kernel<<<M_TOK / 8, 256>>>(out, n2s, n2b);
}

// round 6
// speedup vs baseline: 3.4757x; 1.0359x over previous
#include <cuda_runtime.h>
#include <cuda_fp16.h>
#include <math.h>
#include <stdint.h>

#define M_TOK 131072          // 32 * 4096 tokens

// ---------------- device scratch ----------------
__device__ float  g_bufA[M_TOK * 256];          // proj output (fp32)
__device__ float  g_y2  [M_TOK * 256];          // fc2 output (fp32)
__device__ float  g_x1  [M_TOK * 256];          // first residual (fp32)
__device__ __half g_qkvh[M_TOK * 768];          // packed qkv (half)
__device__ __half g_xh  [M_TOK * 256];          // gathered x (half)  -> qkv A
__device__ __half g_ah  [M_TOK * 256];          // attn out (half)    -> proj A
__device__ __half g_x1h [M_TOK * 256];          // x1 (half)          -> fc1 A
__device__ __half g_hh  [M_TOK * 1024];         // gelu hidden (half) -> fc2 A
__device__ __half g_wTh [786432];               // transposed weights [N][K] half
__device__ float  g_bias768[768];
__device__ float  g_btab[225 * 8];
__device__ float  g_rpb [8 * 64 * 64];

#define WT_QKV  0
#define WT_PROJ 196608
#define WT_FC1  262144
#define WT_FC2  524288

// ---------------- helpers ----------------
__device__ __forceinline__ uint32_t smem_u32(const void* p) {
    uint32_t a;
    asm("{ .reg .u64 t; cvta.to.shared.u64 t, %1; cvt.u32.u64 %0, t; }"
        : "=r"(a) : "l"(p));
    return a;
}

__device__ __forceinline__ void cp16(uint32_t dst, const void* src) {
    asm volatile("cp.async.cg.shared.global [%0], [%1], 16;" :: "r"(dst), "l"(src) : "memory");
}

__device__ __forceinline__ void ldsm_x4(uint32_t& r0, uint32_t& r1, uint32_t& r2,
                                        uint32_t& r3, uint32_t addr) {
    asm volatile("ldmatrix.sync.aligned.m8n8.x4.shared.b16 {%0,%1,%2,%3}, [%4];"
                 : "=r"(r0), "=r"(r1), "=r"(r2), "=r"(r3) : "r"(addr));
}

__device__ __forceinline__ void mma16816(float& d0, float& d1, float& d2, float& d3,
                                         uint32_t a0, uint32_t a1, uint32_t a2, uint32_t a3,
                                         uint32_t b0, uint32_t b1) {
    asm volatile("mma.sync.aligned.m16n8k16.row.col.f32.f16.f16.f32 "
                 "{%0,%1,%2,%3}, {%4,%5,%6,%7}, {%8,%9}, {%0,%1,%2,%3};"
                 : "+f"(d0), "+f"(d1), "+f"(d2), "+f"(d3)
                 : "r"(a0), "r"(a1), "r"(a2), "r"(a3), "r"(b0), "r"(b1));
}

#define SWZ(x) ((x) ^ (((x) >> 3) & 0x70))

__device__ __forceinline__ float gelu_f(float x) {
    float y = 0.7978845608028654f * (x + 0.044715f * x * x * x);
    float t = 1.f - 2.f / (__expf(2.f * y) + 1.f);
    return 0.5f * x * (1.f + t);
}

// ---------------- tiny precompute kernels ----------------
__global__ void pack_bias_kernel(const float* __restrict__ qb,
                                 const float* __restrict__ vb) {
    int i = threadIdx.x;
    float v = 0.f;
    if (i < 256)       v = qb[i];
    else if (i >= 512) v = vb[i - 512];
    g_bias768[i] = v;
}

__global__ void __launch_bounds__(512) cpb_kernel(const float* __restrict__ w1,
                                                  const float* __restrict__ b1,
                                                  const float* __restrict__ w2) {
    int p = blockIdx.x;
    int i = p / 15, j = p % 15;
    float t0 = (float)(i - 7) * (8.f / 7.f), t1 = (float)(j - 7) * (8.f / 7.f);
    t0 = copysignf(log2f(fabsf(t0) + 1.f) * (1.f / 3.f), t0);
    t1 = copysignf(log2f(fabsf(t1) + 1.f) * (1.f / 3.f), t1);

    int jt = threadIdx.x;
    float hidden = fmaxf(t0 * w1[jt] + t1 * w1[512 + jt] + b1[jt], 0.f);

    __shared__ float sh[512];
    for (int h = 0; h < 8; h++) {
        sh[jt] = hidden * w2[jt * 8 + h];
        __syncthreads();
        for (int off = 256; off > 0; off >>= 1) {
            if (jt < off) sh[jt] += sh[jt + off];
            __syncthreads();
        }
        if (jt == 0) g_btab[p * 8 + h] = sh[0];
        __syncthreads();
    }
}

__global__ void rpb_kernel() {
    int n = blockIdx.x, h = blockIdx.y, m = threadIdx.x;
    int dr = (n >> 3) - (m >> 3) + 7;
    int dc = (n & 7)  - (m & 7)  + 7;
    float v = g_btab[(dr * 15 + dc) * 8 + h];
    g_rpb[h * 4096 + n * 64 + m] = 16.f / (1.f + expf(-v));
}

// src[K][N] fp32 -> dst[N][K] half
__global__ void transpose_kernel(const float* __restrict__ src, __half* __restrict__ dst,
                                 int K, int N) {
    __shared__ float t[32][33];
    int kb = blockIdx.y * 32, nb = blockIdx.x * 32;
#pragma unroll
    for (int i = 0; i < 4; i++)
        t[threadIdx.y + 8 * i][threadIdx.x] =
            src[(size_t)(kb + threadIdx.y + 8 * i) * N + nb + threadIdx.x];
    __syncthreads();
#pragma unroll
    for (int i = 0; i < 4; i++)
        dst[(size_t)(nb + threadIdx.y + 8 * i) * K + kb + threadIdx.x] =
            __float2half(t[threadIdx.x][threadIdx.y + 8 * i]);
}

// ---------------- cyclic shift + window partition gather -> half ----------------
__global__ void gather_kernel(const float* __restrict__ x) {
    int idx = blockIdx.x * 256 + threadIdx.x;
    int row = idx >> 6;
    int qd  = idx & 63;
    int b   = row >> 12;
    int rem = row & 4095;
    int win = rem >> 6;
    int n   = rem & 63;
    int hs  = (win >> 3) * 8 + (n >> 3);
    int ws  = (win & 7)  * 8 + (n & 7);
    int hsrc = (hs + 4) & 63;
    int wsrc = (ws + 4) & 63;
    int src  = b * 4096 + hsrc * 64 + wsrc;
    float4 v = ((const float4*)x)[(size_t)src * 64 + qd];
    __half2 h0 = __float22half2_rn(make_float2(v.x, v.y));
    __half2 h1 = __float22half2_rn(make_float2(v.z, v.w));
    uint2 pk = make_uint2(*(uint32_t*)&h0, *(uint32_t*)&h1);
    ((uint2*)g_xh)[(size_t)row * 64 + qd] = pk;
}

// ---------------- FP16 HMMA GEMM ----------------
// Cf/Ch (M x N) = A(M x K half) * Bt(N x K half)^T + bias.
// BM=128, BN=128, BK=64 halves; 256 threads (8 warps, 2x4); warp tile 64x32.
template <int ACT, int WF, int WH>
__global__ void __launch_bounds__(256) gemm_h(const __half* __restrict__ A,
                                              const __half* __restrict__ Bt,
                                              const float* __restrict__ bias,
                                              float* __restrict__ Cf,
                                              __half* __restrict__ Ch,
                                              int N, int K) {
    extern __shared__ char smem[];
    uint32_t base = (smem_u32(smem) + 1023u) & ~1023u;
    const int tid  = threadIdx.x;
    const int warp = tid >> 5;
    const int lane = tid & 31;
    const int wm   = warp >> 2;            // 0..1
    const int wn   = warp & 3;             // 0..3
    const int row0 = blockIdx.y * 128;
    const int col0 = blockIdx.x * 128;
    const int chunks = K >> 6;

    const int cp_row = tid >> 3;           // 0..31
    const int cp_c   = tid & 7;            // 16B chunk

    float acc[4][4][4];
#pragma unroll
    for (int i = 0; i < 4; i++)
#pragma unroll
        for (int j = 0; j < 4; j++)
#pragma unroll
            for (int e = 0; e < 4; e++) acc[i][j][e] = 0.f;

    // A ldmatrix bases: per mtl, lane -> row = wm*64+mtl*16+(lane&15), byte=(lane>>4)*16
    uint32_t a_base[4], a_x[4];
#pragma unroll
    for (int mtl = 0; mtl < 4; mtl++) {
        int r = wm * 64 + mtl * 16 + (lane & 15);
        a_base[mtl] = r * 128 + ((lane >> 4) * 16);
        a_x[mtl]    = (r & 7) * 16;
    }
    // B ldmatrix bases (x4 covers two ntl): g=lane>>3 -> ntl=2p+(g>>1), byte=(g&1)*16
    uint32_t b_base[2], b_x;
    {
        int g = lane >> 3;
#pragma unroll
        for (int p = 0; p < 2; p++) {
            int r = wn * 32 + (2 * p + (g >> 1)) * 8 + (lane & 7);
            b_base[p] = r * 128 + ((g & 1) * 16);
        }
        b_x = (lane & 7) * 16;
    }

    // prefetch chunk 0 into stage 0
    {
        uint32_t aB = base, bB = base + 16384u;
#pragma unroll
        for (int i = 0; i < 4; i++) {
            int row = cp_row + i * 32;
            cp16(aB + SWZ(row * 128 + cp_c * 16), A  + (size_t)(row0 + row) * K + cp_c * 8);
            cp16(bB + SWZ(row * 128 + cp_c * 16), Bt + (size_t)(col0 + row) * K + cp_c * 8);
        }
        asm volatile("cp.async.commit_group;" ::: "memory");
    }

    for (int c = 0; c < chunks; c++) {
        if (c + 1 < chunks) {
            uint32_t st = ((c + 1) & 1) * 32768u;
            uint32_t aB = base + st, bB = base + 16384u + st;
            int kk = (c + 1) * 64;
#pragma unroll
            for (int i = 0; i < 4; i++) {
                int row = cp_row + i * 32;
                cp16(aB + SWZ(row * 128 + cp_c * 16),
                     A  + (size_t)(row0 + row) * K + kk + cp_c * 8);
                cp16(bB + SWZ(row * 128 + cp_c * 16),
                     Bt + (size_t)(col0 + row) * K + kk + cp_c * 8);
            }
            asm volatile("cp.async.commit_group;" ::: "memory");
            asm volatile("cp.async.wait_group 1;" ::: "memory");
        } else {
            asm volatile("cp.async.wait_group 0;" ::: "memory");
        }
        __syncthreads();

        uint32_t st = (c & 1) * 32768u;
        uint32_t aCur = base + st, bCur = base + 16384u + st;
#pragma unroll
        for (int ks = 0; ks < 4; ks++) {
            uint32_t ko = ks << 5;         // 32 bytes per k-step
            uint32_t af[4][4];
            uint32_t bf[4][2];
#pragma unroll
            for (int mtl = 0; mtl < 4; mtl++)
                ldsm_x4(af[mtl][0], af[mtl][1], af[mtl][2], af[mtl][3],
                        aCur + ((a_base[mtl] + ko) ^ a_x[mtl]));
#pragma unroll
            for (int p = 0; p < 2; p++)
                ldsm_x4(bf[2 * p][0], bf[2 * p][1], bf[2 * p + 1][0], bf[2 * p + 1][1],
                        bCur + ((b_base[p] + ko) ^ b_x));
#pragma unroll
            for (int mtl = 0; mtl < 4; mtl++)
#pragma unroll
                for (int ntl = 0; ntl < 4; ntl++)
                    mma16816(acc[mtl][ntl][0], acc[mtl][ntl][1],
                             acc[mtl][ntl][2], acc[mtl][ntl][3],
                             af[mtl][0], af[mtl][1], af[mtl][2], af[mtl][3],
                             bf[ntl][0], bf[ntl][1]);
        }
        __syncthreads();
    }

    // epilogue
#pragma unroll
    for (int mtl = 0; mtl < 4; mtl++) {
        int rbase = row0 + wm * 64 + mtl * 16 + (lane >> 2);
#pragma unroll
        for (int ntl = 0; ntl < 4; ntl++) {
            int cc = col0 + wn * 32 + ntl * 8 + (lane & 3) * 2;
            float b0 = bias[cc], b1 = bias[cc + 1];
#pragma unroll
            for (int half = 0; half < 2; half++) {
                int r = rbase + half * 8;
                float v0 = acc[mtl][ntl][half * 2 + 0] + b0;
                float v1 = acc[mtl][ntl][half * 2 + 1] + b1;
                if (ACT == 1) { v0 = gelu_f(v0); v1 = gelu_f(v1); }
                if (WF)
                    *(float2*)(Cf + (size_t)r * N + cc) = make_float2(v0, v1);
                if (WH) {
                    __half2 hv = __float22half2_rn(make_float2(v0, v1));
                    *(uint32_t*)(Ch + (size_t)r * N + cc) = *(uint32_t*)&hv;
                }
            }
        }
    }
}

// ---------------- window attention (qkv in half) ----------------
__device__ __forceinline__ void load_row32(const __half* p, float* out) {
    const uint4* q = (const uint4*)p;
#pragma unroll
    for (int i = 0; i < 2; i++) {
        uint4 u = q[i];
        float2 f0 = __half22float2(*(__half2*)&u.x);
        float2 f1 = __half22float2(*(__half2*)&u.y);
        float2 f2 = __half22float2(*(__half2*)&u.z);
        float2 f3 = __half22float2(*(__half2*)&u.w);
        out[i * 8 + 0] = f0.x; out[i * 8 + 1] = f0.y;
        out[i * 8 + 2] = f1.x; out[i * 8 + 3] = f1.y;
        out[i * 8 + 4] = f2.x; out[i * 8 + 5] = f2.y;
        out[i * 8 + 6] = f3.x; out[i * 8 + 7] = f3.y;
    }
    const uint4* q2 = q + 2;
#pragma unroll
    for (int i = 0; i < 2; i++) {
        uint4 u = q2[i];
        float2 f0 = __half22float2(*(__half2*)&u.x);
        float2 f1 = __half22float2(*(__half2*)&u.y);
        float2 f2 = __half22float2(*(__half2*)&u.z);
        float2 f3 = __half22float2(*(__half2*)&u.w);
        out[16 + i * 8 + 0] = f0.x; out[16 + i * 8 + 1] = f0.y;
        out[16 + i * 8 + 2] = f1.x; out[16 + i * 8 + 3] = f1.y;
        out[16 + i * 8 + 4] = f2.x; out[16 + i * 8 + 5] = f2.y;
        out[16 + i * 8 + 6] = f3.x; out[16 + i * 8 + 7] = f3.y;
    }
}

__global__ void __launch_bounds__(64) attn_kernel(const float* __restrict__ logit_scale) {
    int bi = blockIdx.x;
    int b_ = bi >> 3;
    int hh = bi & 7;
    int n  = threadIdx.x;
    int win = b_ & 63;
    int wh = win >> 3, ww = win & 7;

    __shared__ float4 sk4[64][8];
    __shared__ float4 sv4[64][8];
    __shared__ int    sreg[64];

    const __half* base = g_qkvh + (size_t)(b_ * 64) * 768;

    float q[32], kr[32], vr[32];
    load_row32(base + (size_t)n * 768 + hh * 32, q);
    load_row32(base + (size_t)n * 768 + 256 + hh * 32, kr);
    load_row32(base + (size_t)n * 768 + 512 + hh * 32, vr);

    {
        float ss = 0.f;
#pragma unroll
        for (int d = 0; d < 32; d++) ss += q[d] * q[d];
        float rn = rsqrtf(fmaxf(ss, 1e-12f));
#pragma unroll
        for (int d = 0; d < 32; d++) q[d] *= rn;
    }
    {
        float ks = 0.f;
#pragma unroll
        for (int d = 0; d < 32; d++) ks += kr[d] * kr[d];
        float rk = rsqrtf(fmaxf(ks, 1e-12f));
#pragma unroll
        for (int j = 0; j < 8; j++)
            sk4[n][j] = make_float4(kr[4*j] * rk, kr[4*j+1] * rk,
                                    kr[4*j+2] * rk, kr[4*j+3] * rk);
    }
#pragma unroll
    for (int j = 0; j < 8; j++)
        sv4[n][j] = make_float4(vr[4*j], vr[4*j+1], vr[4*j+2], vr[4*j+3]);
    {
        int r = n >> 3, c = n & 7;
        int habs = wh * 8 + r, wabs = ww * 8 + c;
        int rh = habs < 56 ? 0 : (habs < 60 ? 1 : 2);
        int rw = wabs < 56 ? 0 : (wabs < 60 ? 1 : 2);
        sreg[n] = rh * 3 + rw;
    }
    __syncthreads();

    float scale = __expf(fminf(logit_scale[hh], 4.605170185988092f));
    int myreg = sreg[n];
    const float* rpb = g_rpb + hh * 4096 + n * 64;

    float a[64];
    float amax = -1e30f;
#pragma unroll
    for (int m = 0; m < 64; m++) {
        float dot = 0.f;
#pragma unroll
        for (int j = 0; j < 8; j++) {
            float4 kk = sk4[m][j];
            dot += q[4*j] * kk.x + q[4*j+1] * kk.y + q[4*j+2] * kk.z + q[4*j+3] * kk.w;
        }
        float v = dot * scale + rpb[m];
        if (sreg[m] != myreg) v -= 100.f;
        a[m] = v;
        amax = fmaxf(amax, v);
    }
    float asum = 0.f;
#pragma unroll
    for (int m = 0; m < 64; m++) { a[m] = __expf(a[m] - amax); asum += a[m]; }
    float inv = 1.f / asum;

    float4 o[8];
#pragma unroll
    for (int j = 0; j < 8; j++) o[j] = make_float4(0.f, 0.f, 0.f, 0.f);
#pragma unroll
    for (int m = 0; m < 64; m++) {
        float am = a[m] * inv;
#pragma unroll
        for (int j = 0; j < 8; j++) {
            float4 vv = sv4[m][j];
            o[j].x += am * vv.x; o[j].y += am * vv.y;
            o[j].z += am * vv.z; o[j].w += am * vv.w;
        }
    }
    uint2* op = (uint2*)(g_ah + (size_t)(b_ * 64 + n) * 256 + hh * 32);
#pragma unroll
    for (int j = 0; j < 8; j++) {
        __half2 h0 = __float22half2_rn(make_float2(o[j].x, o[j].y));
        __half2 h1 = __float22half2_rn(make_float2(o[j].z, o[j].w));
        op[j] = make_uint2(*(uint32_t*)&h0, *(uint32_t*)&h1);
    }
}

// ---------------- LN + residual (branch 1) ----------------
__global__ void __launch_bounds__(256) ln1_kernel(const float* __restrict__ x,
                                                  const float* __restrict__ scale,
                                                  const float* __restrict__ bias) {
    int warp = threadIdx.x >> 5;
    int lane = threadIdx.x & 31;
    int t = blockIdx.x * 8 + warp;
    int b = t >> 12;
    int hw = t & 4095;
    int h = hw >> 6, w = hw & 63;
    int hs = (h + 60) & 63;
    int ws = (w + 60) & 63;
    int src = b * 4096 + ((hs >> 3) * 8 + (ws >> 3)) * 64 + ((hs & 7) * 8 + (ws & 7));

    const float* yp = g_bufA + (size_t)src * 256;
    float y[8]; float s = 0.f;
#pragma unroll
    for (int k = 0; k < 8; k++) { y[k] = yp[lane + 32 * k]; s += y[k]; }
#pragma unroll
    for (int o = 16; o > 0; o >>= 1) s += __shfl_xor_sync(0xffffffffu, s, o);
    float mu = s * (1.f / 256.f);
    float vs = 0.f;
#pragma unroll
    for (int k = 0; k < 8; k++) { float d = y[k] - mu; vs += d * d; }
#pragma unroll
    for (int o = 16; o > 0; o >>= 1) vs += __shfl_xor_sync(0xffffffffu, vs, o);
    float rstd = rsqrtf(vs * (1.f / 256.f) + 1e-6f);

    const float* xp = x + (size_t)t * 256;
    float*  op  = g_x1  + (size_t)t * 256;
    __half* oph = g_x1h + (size_t)t * 256;
#pragma unroll
    for (int k = 0; k < 8; k++) {
        int c = lane + 32 * k;
        float v = xp[c] + (y[k] - mu) * rstd * scale[c] + bias[c];
        op[c]  = v;
        oph[c] = __float2half(v);
    }
}

// ---------------- final: out = x1 + LN(fc2_out) ----------------
__global__ void __launch_bounds__(256) final_kernel(float* __restrict__ out,
                                                    const float* __restrict__ scale,
                                                    const float* __restrict__ bias) {
    int warp = threadIdx.x >> 5;
    int lane = threadIdx.x & 31;
    int t = blockIdx.x * 8 + warp;

    const float* yp = g_y2 + (size_t)t * 256;
    float y[8]; float s = 0.f;
#pragma unroll
    for (int k = 0; k < 8; k++) { y[k] = yp[lane + 32 * k]; s += y[k]; }
#pragma unroll
    for (int o = 16; o > 0; o >>= 1) s += __shfl_xor_sync(0xffffffffu, s, o);
    float mu = s * (1.f / 256.f);
    float vs = 0.f;
#pragma unroll
    for (int k = 0; k < 8; k++) { float d = y[k] - mu; vs += d * d; }
#pragma unroll
    for (int o = 16; o > 0; o >>= 1) vs += __shfl_xor_sync(0xffffffffu, vs, o);
    float rstd = rsqrtf(vs * (1.f / 256.f) + 1e-6f);

    const float* x1p = g_x1 + (size_t)t * 256;
    float* op = out + (size_t)t * 256;
#pragma unroll
    for (int k = 0; k < 8; k++) {
        int c = lane + 32 * k;
        op[c] = x1p[c] + (y[k] - mu) * rstd * scale[c] + bias[c];
    }
}

// ---------------- launch ----------------
#define GEMM_SMEM (65536 + 1024)

extern "C" void kernel_launch(void* const* d_in, const int* in_sizes, int n_in,
                              void* d_out, int out_size) {
    const float* x      = (const float*)d_in[0];
    const float* qkv_w  = (const float*)d_in[1];
    const float* q_bias = (const float*)d_in[2];
    const float* v_bias = (const float*)d_in[3];
    const float* lscale = (const float*)d_in[4];
    const float* cpb_w1 = (const float*)d_in[5];
    const float* cpb_b1 = (const float*)d_in[6];
    const float* cpb_w2 = (const float*)d_in[7];
    const float* proj_w = (const float*)d_in[8];
    const float* proj_b = (const float*)d_in[9];
    const float* n1s    = (const float*)d_in[10];
    const float* n1b    = (const float*)d_in[11];
    const float* n2s    = (const float*)d_in[12];
    const float* n2b    = (const float*)d_in[13];
    const float* fc1_w  = (const float*)d_in[14];
    const float* fc1_b  = (const float*)d_in[15];
    const float* fc2_w  = (const float*)d_in[16];
    const float* fc2_b  = (const float*)d_in[17];
    float* out = (float*)d_out;

    float *pA, *pY2, *pB768;
    __half *pXh, *pAh, *pX1h, *pHh, *pWTh, *pQkvh;
    cudaGetSymbolAddress((void**)&pA,    g_bufA);
    cudaGetSymbolAddress((void**)&pY2,   g_y2);
    cudaGetSymbolAddress((void**)&pB768, g_bias768);
    cudaGetSymbolAddress((void**)&pXh,   g_xh);
    cudaGetSymbolAddress((void**)&pAh,   g_ah);
    cudaGetSymbolAddress((void**)&pX1h,  g_x1h);
    cudaGetSymbolAddress((void**)&pHh,   g_hh);
    cudaGetSymbolAddress((void**)&pWTh,  g_wTh);
    cudaGetSymbolAddress((void**)&pQkvh, g_qkvh);

    cudaFuncSetAttribute(gemm_h<0,1,0>, cudaFuncAttributeMaxDynamicSharedMemorySize, GEMM_SMEM);
    cudaFuncSetAttribute(gemm_h<0,0,1>, cudaFuncAttributeMaxDynamicSharedMemorySize, GEMM_SMEM);
    cudaFuncSetAttribute(gemm_h<1,0,1>, cudaFuncAttributeMaxDynamicSharedMemorySize, GEMM_SMEM);

    pack_bias_kernel<<<1, 768>>>(q_bias, v_bias);
    cpb_kernel<<<225, 512>>>(cpb_w1, cpb_b1, cpb_w2);
    rpb_kernel<<<dim3(64, 8), 64>>>();

    transpose_kernel<<<dim3(768 / 32, 256 / 32),  dim3(32, 8)>>>(qkv_w,  pWTh + WT_QKV,  256, 768);
    transpose_kernel<<<dim3(256 / 32, 256 / 32),  dim3(32, 8)>>>(proj_w, pWTh + WT_PROJ, 256, 256);
    transpose_kernel<<<dim3(1024 / 32, 256 / 32), dim3(32, 8)>>>(fc1_w,  pWTh + WT_FC1,  256, 1024);
    transpose_kernel<<<dim3(256 / 32, 1024 / 32), dim3(32, 8)>>>(fc2_w,  pWTh + WT_FC2,  1024, 256);

    gather_kernel<<<M_TOK * 64 / 256, 256>>>(x);

    // qkv: (M,256)x(256,768) -> half g_qkvh
    gemm_h<0,0,1><<<dim3(6, M_TOK / 128), 256, GEMM_SMEM>>>(
        pXh, pWTh + WT_QKV, pB768, (float*)0, pQkvh, 768, 256);
    attn_kernel<<<2048 * 8, 64>>>(lscale);

    // proj: (M,256)x(256,256) -> fp32 g_bufA
    gemm_h<0,1,0><<<dim3(2, M_TOK / 128), 256, GEMM_SMEM>>>(
        pAh, pWTh + WT_PROJ, proj_b, pA, (__half*)0, 256, 256);
    ln1_kernel<<<M_TOK / 8, 256>>>(x, n1s, n1b);

    // fc1+gelu: (M,256)x(256,1024) -> half g_hh
    gemm_h<1,0,1><<<dim3(8, M_TOK / 128), 256, GEMM_SMEM>>>(
        pX1h, pWTh + WT_FC1, fc1_b, (float*)0, pHh, 1024, 256);
    // fc2: (M,1024)x(1024,256) -> fp32 g_y2
    gemm_h<0,1,0><<<dim3(2, M_TOK / 128), 256, GEMM_SMEM>>>(
        pHh, pWTh + WT_FC2, fc2_b, pY2, (__half*)0, 256, 1024);
    final_kernel<<<M_TOK / 8, 256>>>(out, n2s, n2b);
}

// round 11
// speedup vs baseline: 3.6401x; 1.0473x over previous
#include <cuda_runtime.h>
#include <cuda_fp16.h>
#include <math.h>
#include <stdint.h>

#define M_TOK 131072          // 32 * 4096 tokens

// ---------------- device scratch ----------------
__device__ float  g_bufA[M_TOK * 256];          // proj output (fp32)
__device__ float  g_y2  [M_TOK * 256];          // fc2 output (fp32)
__device__ float  g_x1  [M_TOK * 256];          // first residual (fp32)
__device__ __half g_qkvh[M_TOK * 768];          // packed qkv (half)
__device__ __half g_xh  [M_TOK * 256];          // gathered x (half)  -> qkv A
__device__ __half g_ah  [M_TOK * 256];          // attn out (half)    -> proj A
__device__ __half g_x1h [M_TOK * 256];          // x1 (half)          -> fc1 A
__device__ __half g_hh  [M_TOK * 1024];         // gelu hidden (half) -> fc2 A
__device__ __half g_wTh [786432];               // transposed weights [N][K] half
__device__ float  g_bias768[768];
__device__ float  g_btab[225 * 8];
__device__ float  g_rpb [8 * 64 * 64];

#define WT_QKV  0
#define WT_PROJ 196608
#define WT_FC1  262144
#define WT_FC2  524288

// ---------------- helpers ----------------
__device__ __forceinline__ uint32_t smem_u32(const void* p) {
    uint32_t a;
    asm("{ .reg .u64 t; cvta.to.shared.u64 t, %1; cvt.u32.u64 %0, t; }"
        : "=r"(a) : "l"(p));
    return a;
}

__device__ __forceinline__ void cp16(uint32_t dst, const void* src) {
    asm volatile("cp.async.cg.shared.global [%0], [%1], 16;" :: "r"(dst), "l"(src) : "memory");
}

__device__ __forceinline__ void ldsm_x4(uint32_t& r0, uint32_t& r1, uint32_t& r2,
                                        uint32_t& r3, uint32_t addr) {
    asm volatile("ldmatrix.sync.aligned.m8n8.x4.shared.b16 {%0,%1,%2,%3}, [%4];"
                 : "=r"(r0), "=r"(r1), "=r"(r2), "=r"(r3) : "r"(addr));
}

__device__ __forceinline__ void mma16816(float& d0, float& d1, float& d2, float& d3,
                                         uint32_t a0, uint32_t a1, uint32_t a2, uint32_t a3,
                                         uint32_t b0, uint32_t b1) {
    asm volatile("mma.sync.aligned.m16n8k16.row.col.f32.f16.f16.f32 "
                 "{%0,%1,%2,%3}, {%4,%5,%6,%7}, {%8,%9}, {%0,%1,%2,%3};"
                 : "+f"(d0), "+f"(d1), "+f"(d2), "+f"(d3)
                 : "r"(a0), "r"(a1), "r"(a2), "r"(a3), "r"(b0), "r"(b1));
}

#define SWZ(x) ((x) ^ (((x) >> 3) & 0x70))

__device__ __forceinline__ float gelu_f(float x) {
    float y = 0.7978845608028654f * (x + 0.044715f * x * x * x);
    float t = 1.f - 2.f / (__expf(2.f * y) + 1.f);
    return 0.5f * x * (1.f + t);
}

// ---------------- tiny precompute kernels ----------------
__global__ void pack_bias_kernel(const float* __restrict__ qb,
                                 const float* __restrict__ vb) {
    int i = threadIdx.x;
    float v = 0.f;
    if (i < 256)       v = qb[i];
    else if (i >= 512) v = vb[i - 512];
    g_bias768[i] = v;
}

__global__ void __launch_bounds__(512) cpb_kernel(const float* __restrict__ w1,
                                                  const float* __restrict__ b1,
                                                  const float* __restrict__ w2) {
    int p = blockIdx.x;
    int i = p / 15, j = p % 15;
    float t0 = (float)(i - 7) * (8.f / 7.f), t1 = (float)(j - 7) * (8.f / 7.f);
    t0 = copysignf(log2f(fabsf(t0) + 1.f) * (1.f / 3.f), t0);
    t1 = copysignf(log2f(fabsf(t1) + 1.f) * (1.f / 3.f), t1);

    int jt = threadIdx.x;
    float hidden = fmaxf(t0 * w1[jt] + t1 * w1[512 + jt] + b1[jt], 0.f);

    __shared__ float sh[512];
    for (int h = 0; h < 8; h++) {
        sh[jt] = hidden * w2[jt * 8 + h];
        __syncthreads();
        for (int off = 256; off > 0; off >>= 1) {
            if (jt < off) sh[jt] += sh[jt + off];
            __syncthreads();
        }
        if (jt == 0) g_btab[p * 8 + h] = sh[0];
        __syncthreads();
    }
}

__global__ void rpb_kernel() {
    int n = blockIdx.x, h = blockIdx.y, m = threadIdx.x;
    int dr = (n >> 3) - (m >> 3) + 7;
    int dc = (n & 7)  - (m & 7)  + 7;
    float v = g_btab[(dr * 15 + dc) * 8 + h];
    g_rpb[h * 4096 + n * 64 + m] = 16.f / (1.f + expf(-v));
}

// src[K][N] fp32 -> dst[N][K] half
__global__ void transpose_kernel(const float* __restrict__ src, __half* __restrict__ dst,
                                 int K, int N) {
    __shared__ float t[32][33];
    int kb = blockIdx.y * 32, nb = blockIdx.x * 32;
#pragma unroll
    for (int i = 0; i < 4; i++)
        t[threadIdx.y + 8 * i][threadIdx.x] =
            src[(size_t)(kb + threadIdx.y + 8 * i) * N + nb + threadIdx.x];
    __syncthreads();
#pragma unroll
    for (int i = 0; i < 4; i++)
        dst[(size_t)(nb + threadIdx.y + 8 * i) * K + kb + threadIdx.x] =
            __float2half(t[threadIdx.x][threadIdx.y + 8 * i]);
}

// ---------------- cyclic shift + window partition gather -> half ----------------
__global__ void gather_kernel(const float* __restrict__ x) {
    int idx = blockIdx.x * 256 + threadIdx.x;
    int row = idx >> 6;
    int qd  = idx & 63;
    int b   = row >> 12;
    int rem = row & 4095;
    int win = rem >> 6;
    int n   = rem & 63;
    int hs  = (win >> 3) * 8 + (n >> 3);
    int ws  = (win & 7)  * 8 + (n & 7);
    int hsrc = (hs + 4) & 63;
    int wsrc = (ws + 4) & 63;
    int src  = b * 4096 + hsrc * 64 + wsrc;
    float4 v = ((const float4*)x)[(size_t)src * 64 + qd];
    __half2 h0 = __float22half2_rn(make_float2(v.x, v.y));
    __half2 h1 = __float22half2_rn(make_float2(v.z, v.w));
    uint2 pk = make_uint2(*(uint32_t*)&h0, *(uint32_t*)&h1);
    ((uint2*)g_xh)[(size_t)row * 64 + qd] = pk;
}

// ================= A-resident FP16 GEMM (K = 256) =================
// Block computes rows [row0,row0+128) for ALL N columns.
// A tile (128 x 256 half, 64KB) resident in smem; B tiles (128 x 256, 64KB)
// double-buffered. Rows have 512B pitch, 16B-chunk xor swizzle by (row&7).

__device__ __forceinline__ void stage_tile256(uint32_t dst, const __half* __restrict__ src) {
    int tid = threadIdx.x;
#pragma unroll
    for (int i = 0; i < 16; i++) {
        int id  = tid + 256 * i;
        int row = id >> 5, c = id & 31;
        cp16(dst + row * 512 + ((c ^ (row & 7)) << 4), src + (size_t)row * 256 + c * 8);
    }
}

template <int ACT, int WF, int WH>
__global__ void __launch_bounds__(256) gemm_ares(const __half* __restrict__ A,
                                                 const __half* __restrict__ Bt,
                                                 const float* __restrict__ bias,
                                                 float* __restrict__ Cf,
                                                 __half* __restrict__ Ch,
                                                 int N) {
    extern __shared__ char smem[];
    uint32_t base  = (smem_u32(smem) + 1023u) & ~1023u;
    uint32_t aBuf  = base;
    uint32_t bBuf0 = base + 65536u;
    uint32_t bBuf1 = base + 131072u;

    const int tid  = threadIdx.x;
    const int warp = tid >> 5;
    const int lane = tid & 31;
    const int wm   = warp >> 2;
    const int wn   = warp & 3;
    const int row0 = blockIdx.x * 128;
    const int ntiles = N >> 7;

    stage_tile256(aBuf, A + (size_t)row0 * 256);
    stage_tile256(bBuf0, Bt);
    asm volatile("cp.async.commit_group;" ::: "memory");
    if (ntiles > 1) {
        stage_tile256(bBuf1, Bt + (size_t)128 * 256);
        asm volatile("cp.async.commit_group;" ::: "memory");
    }

    uint32_t a_row[4]; int a_sw[4];
#pragma unroll
    for (int mtl = 0; mtl < 4; mtl++) {
        int r = wm * 64 + mtl * 16 + (lane & 15);
        a_row[mtl] = r * 512;
        a_sw[mtl]  = r & 7;
    }
    const int a_half = lane >> 4;
    uint32_t b_row[2]; int b_sw[2];
    const int g = lane >> 3;
#pragma unroll
    for (int p = 0; p < 2; p++) {
        int r = wn * 32 + (2 * p + (g >> 1)) * 8 + (lane & 7);
        b_row[p] = r * 512;
        b_sw[p]  = r & 7;
    }
    const int b_half = g & 1;

    for (int nt = 0; nt < ntiles; nt++) {
        if (nt + 1 < ntiles)
            asm volatile("cp.async.wait_group 1;" ::: "memory");
        else
            asm volatile("cp.async.wait_group 0;" ::: "memory");
        __syncthreads();

        uint32_t bCur = (nt & 1) ? bBuf1 : bBuf0;

        float acc[4][4][4];
#pragma unroll
        for (int i = 0; i < 4; i++)
#pragma unroll
            for (int j = 0; j < 4; j++)
#pragma unroll
                for (int e = 0; e < 4; e++) acc[i][j][e] = 0.f;

#pragma unroll
        for (int ks = 0; ks < 16; ks++) {
            uint32_t af[4][4];
            uint32_t bf[4][2];
#pragma unroll
            for (int mtl = 0; mtl < 4; mtl++) {
                uint32_t addr = aBuf + a_row[mtl] +
                                (uint32_t)(((ks * 2 + a_half) ^ a_sw[mtl]) << 4);
                ldsm_x4(af[mtl][0], af[mtl][1], af[mtl][2], af[mtl][3], addr);
            }
#pragma unroll
            for (int p = 0; p < 2; p++) {
                uint32_t addr = bCur + b_row[p] +
                                (uint32_t)(((ks * 2 + b_half) ^ b_sw[p]) << 4);
                ldsm_x4(bf[2 * p][0], bf[2 * p][1], bf[2 * p + 1][0], bf[2 * p + 1][1], addr);
            }
#pragma unroll
            for (int mtl = 0; mtl < 4; mtl++)
#pragma unroll
                for (int ntl = 0; ntl < 4; ntl++)
                    mma16816(acc[mtl][ntl][0], acc[mtl][ntl][1],
                             acc[mtl][ntl][2], acc[mtl][ntl][3],
                             af[mtl][0], af[mtl][1], af[mtl][2], af[mtl][3],
                             bf[ntl][0], bf[ntl][1]);
        }

        int col0 = nt << 7;
#pragma unroll
        for (int mtl = 0; mtl < 4; mtl++) {
            int rbase = row0 + wm * 64 + mtl * 16 + (lane >> 2);
#pragma unroll
            for (int ntl = 0; ntl < 4; ntl++) {
                int cc = col0 + wn * 32 + ntl * 8 + (lane & 3) * 2;
                float b0 = bias[cc], b1 = bias[cc + 1];
#pragma unroll
                for (int half = 0; half < 2; half++) {
                    int r = rbase + half * 8;
                    float v0 = acc[mtl][ntl][half * 2 + 0] + b0;
                    float v1 = acc[mtl][ntl][half * 2 + 1] + b1;
                    if (ACT == 1) { v0 = gelu_f(v0); v1 = gelu_f(v1); }
                    if (WF)
                        *(float2*)(Cf + (size_t)r * N + cc) = make_float2(v0, v1);
                    if (WH) {
                        __half2 hv = __float22half2_rn(make_float2(v0, v1));
                        *(uint32_t*)(Ch + (size_t)r * N + cc) = *(uint32_t*)&hv;
                    }
                }
            }
        }
        __syncthreads();

        if (nt + 2 < ntiles) {
            stage_tile256(bCur, Bt + (size_t)(nt + 2) * 128 * 256);
            asm volatile("cp.async.commit_group;" ::: "memory");
        }
    }
}

// ================= streamed FP16 GEMM (fc2, K = 1024) =================
template <int ACT, int WF, int WH>
__global__ void __launch_bounds__(256) gemm_h(const __half* __restrict__ A,
                                              const __half* __restrict__ Bt,
                                              const float* __restrict__ bias,
                                              float* __restrict__ Cf,
                                              __half* __restrict__ Ch,
                                              int N, int K) {
    extern __shared__ char smem[];
    uint32_t base = (smem_u32(smem) + 1023u) & ~1023u;
    const int tid  = threadIdx.x;
    const int warp = tid >> 5;
    const int lane = tid & 31;
    const int wm   = warp >> 2;
    const int wn   = warp & 3;
    const int row0 = blockIdx.y * 128;
    const int col0 = blockIdx.x * 128;
    const int chunks = K >> 6;

    const int cp_row = tid >> 3;
    const int cp_c   = tid & 7;

    float acc[4][4][4];
#pragma unroll
    for (int i = 0; i < 4; i++)
#pragma unroll
        for (int j = 0; j < 4; j++)
#pragma unroll
            for (int e = 0; e < 4; e++) acc[i][j][e] = 0.f;

    uint32_t a_base[4], a_x[4];
#pragma unroll
    for (int mtl = 0; mtl < 4; mtl++) {
        int r = wm * 64 + mtl * 16 + (lane & 15);
        a_base[mtl] = r * 128 + ((lane >> 4) * 16);
        a_x[mtl]    = (r & 7) * 16;
    }
    uint32_t b_base[2], b_x;
    {
        int g = lane >> 3;
#pragma unroll
        for (int p = 0; p < 2; p++) {
            int r = wn * 32 + (2 * p + (g >> 1)) * 8 + (lane & 7);
            b_base[p] = r * 128 + ((g & 1) * 16);
        }
        b_x = (lane & 7) * 16;
    }

    {
        uint32_t aB = base, bB = base + 16384u;
#pragma unroll
        for (int i = 0; i < 4; i++) {
            int row = cp_row + i * 32;
            cp16(aB + SWZ(row * 128 + cp_c * 16), A  + (size_t)(row0 + row) * K + cp_c * 8);
            cp16(bB + SWZ(row * 128 + cp_c * 16), Bt + (size_t)(col0 + row) * K + cp_c * 8);
        }
        asm volatile("cp.async.commit_group;" ::: "memory");
    }

    for (int c = 0; c < chunks; c++) {
        if (c + 1 < chunks) {
            uint32_t st = ((c + 1) & 1) * 32768u;
            uint32_t aB = base + st, bB = base + 16384u + st;
            int kk = (c + 1) * 64;
#pragma unroll
            for (int i = 0; i < 4; i++) {
                int row = cp_row + i * 32;
                cp16(aB + SWZ(row * 128 + cp_c * 16),
                     A  + (size_t)(row0 + row) * K + kk + cp_c * 8);
                cp16(bB + SWZ(row * 128 + cp_c * 16),
                     Bt + (size_t)(col0 + row) * K + kk + cp_c * 8);
            }
            asm volatile("cp.async.commit_group;" ::: "memory");
            asm volatile("cp.async.wait_group 1;" ::: "memory");
        } else {
            asm volatile("cp.async.wait_group 0;" ::: "memory");
        }
        __syncthreads();

        uint32_t st = (c & 1) * 32768u;
        uint32_t aCur = base + st, bCur = base + 16384u + st;
#pragma unroll
        for (int ks = 0; ks < 4; ks++) {
            uint32_t ko = ks << 5;
            uint32_t af[4][4];
            uint32_t bf[4][2];
#pragma unroll
            for (int mtl = 0; mtl < 4; mtl++)
                ldsm_x4(af[mtl][0], af[mtl][1], af[mtl][2], af[mtl][3],
                        aCur + ((a_base[mtl] + ko) ^ a_x[mtl]));
#pragma unroll
            for (int p = 0; p < 2; p++)
                ldsm_x4(bf[2 * p][0], bf[2 * p][1], bf[2 * p + 1][0], bf[2 * p + 1][1],
                        bCur + ((b_base[p] + ko) ^ b_x));
#pragma unroll
            for (int mtl = 0; mtl < 4; mtl++)
#pragma unroll
                for (int ntl = 0; ntl < 4; ntl++)
                    mma16816(acc[mtl][ntl][0], acc[mtl][ntl][1],
                             acc[mtl][ntl][2], acc[mtl][ntl][3],
                             af[mtl][0], af[mtl][1], af[mtl][2], af[mtl][3],
                             bf[ntl][0], bf[ntl][1]);
        }
        __syncthreads();
    }

#pragma unroll
    for (int mtl = 0; mtl < 4; mtl++) {
        int rbase = row0 + wm * 64 + mtl * 16 + (lane >> 2);
#pragma unroll
        for (int ntl = 0; ntl < 4; ntl++) {
            int cc = col0 + wn * 32 + ntl * 8 + (lane & 3) * 2;
            float b0 = bias[cc], b1 = bias[cc + 1];
#pragma unroll
            for (int half = 0; half < 2; half++) {
                int r = rbase + half * 8;
                float v0 = acc[mtl][ntl][half * 2 + 0] + b0;
                float v1 = acc[mtl][ntl][half * 2 + 1] + b1;
                if (ACT == 1) { v0 = gelu_f(v0); v1 = gelu_f(v1); }
                if (WF)
                    *(float2*)(Cf + (size_t)r * N + cc) = make_float2(v0, v1);
                if (WH) {
                    __half2 hv = __float22half2_rn(make_float2(v0, v1));
                    *(uint32_t*)(Ch + (size_t)r * N + cc) = *(uint32_t*)&hv;
                }
            }
        }
    }
}

// ---------------- window attention (qkv in half) ----------------
__device__ __forceinline__ void load_row32(const __half* p, float* out) {
    const uint4* q = (const uint4*)p;
#pragma unroll
    for (int i = 0; i < 4; i++) {
        uint4 u = q[i];
        float2 f0 = __half22float2(*(__half2*)&u.x);
        float2 f1 = __half22float2(*(__half2*)&u.y);
        float2 f2 = __half22float2(*(__half2*)&u.z);
        float2 f3 = __half22float2(*(__half2*)&u.w);
        out[i * 8 + 0] = f0.x; out[i * 8 + 1] = f0.y;
        out[i * 8 + 2] = f1.x; out[i * 8 + 3] = f1.y;
        out[i * 8 + 4] = f2.x; out[i * 8 + 5] = f2.y;
        out[i * 8 + 6] = f3.x; out[i * 8 + 7] = f3.y;
    }
}

__global__ void __launch_bounds__(64) attn_kernel(const float* __restrict__ logit_scale) {
    int bi = blockIdx.x;
    int b_ = bi >> 3;
    int hh = bi & 7;
    int n  = threadIdx.x;
    int win = b_ & 63;
    int wh = win >> 3, ww = win & 7;

    __shared__ float4 sk4[64][8];
    __shared__ float4 sv4[64][8];
    __shared__ int    sreg[64];

    const __half* base = g_qkvh + (size_t)(b_ * 64) * 768;

    float q[32], kr[32], vr[32];
    load_row32(base + (size_t)n * 768 + hh * 32, q);
    load_row32(base + (size_t)n * 768 + 256 + hh * 32, kr);
    load_row32(base + (size_t)n * 768 + 512 + hh * 32, vr);

    {
        float ss = 0.f;
#pragma unroll
        for (int d = 0; d < 32; d++) ss += q[d] * q[d];
        float rn = rsqrtf(fmaxf(ss, 1e-12f));
#pragma unroll
        for (int d = 0; d < 32; d++) q[d] *= rn;
    }
    {
        float ks = 0.f;
#pragma unroll
        for (int d = 0; d < 32; d++) ks += kr[d] * kr[d];
        float rk = rsqrtf(fmaxf(ks, 1e-12f));
#pragma unroll
        for (int j = 0; j < 8; j++)
            sk4[n][j] = make_float4(kr[4*j] * rk, kr[4*j+1] * rk,
                                    kr[4*j+2] * rk, kr[4*j+3] * rk);
    }
#pragma unroll
    for (int j = 0; j < 8; j++)
        sv4[n][j] = make_float4(vr[4*j], vr[4*j+1], vr[4*j+2], vr[4*j+3]);
    {
        int r = n >> 3, c = n & 7;
        int habs = wh * 8 + r, wabs = ww * 8 + c;
        int rh = habs < 56 ? 0 : (habs < 60 ? 1 : 2);
        int rw = wabs < 56 ? 0 : (wabs < 60 ? 1 : 2);
        sreg[n] = rh * 3 + rw;
    }
    __syncthreads();

    float scale = __expf(fminf(logit_scale[hh], 4.605170185988092f));
    int myreg = sreg[n];
    const float* rpb = g_rpb + hh * 4096 + n * 64;

    float a[64];
    float amax = -1e30f;
#pragma unroll
    for (int m = 0; m < 64; m++) {
        float dot = 0.f;
#pragma unroll
        for (int j = 0; j < 8; j++) {
            float4 kk = sk4[m][j];
            dot += q[4*j] * kk.x + q[4*j+1] * kk.y + q[4*j+2] * kk.z + q[4*j+3] * kk.w;
        }
        float v = dot * scale + rpb[m];
        if (sreg[m] != myreg) v -= 100.f;
        a[m] = v;
        amax = fmaxf(amax, v);
    }
    float asum = 0.f;
#pragma unroll
    for (int m = 0; m < 64; m++) { a[m] = __expf(a[m] - amax); asum += a[m]; }
    float inv = 1.f / asum;

    float4 o[8];
#pragma unroll
    for (int j = 0; j < 8; j++) o[j] = make_float4(0.f, 0.f, 0.f, 0.f);
#pragma unroll
    for (int m = 0; m < 64; m++) {
        float am = a[m] * inv;
#pragma unroll
        for (int j = 0; j < 8; j++) {
            float4 vv = sv4[m][j];
            o[j].x += am * vv.x; o[j].y += am * vv.y;
            o[j].z += am * vv.z; o[j].w += am * vv.w;
        }
    }
    uint2* op = (uint2*)(g_ah + (size_t)(b_ * 64 + n) * 256 + hh * 32);
#pragma unroll
    for (int j = 0; j < 8; j++) {
        __half2 h0 = __float22half2_rn(make_float2(o[j].x, o[j].y));
        __half2 h1 = __float22half2_rn(make_float2(o[j].z, o[j].w));
        op[j] = make_uint2(*(uint32_t*)&h0, *(uint32_t*)&h1);
    }
}

// ---------------- LN + residual (branch 1) ----------------
__global__ void __launch_bounds__(256) ln1_kernel(const float* __restrict__ x,
                                                  const float* __restrict__ scale,
                                                  const float* __restrict__ bias) {
    int warp = threadIdx.x >> 5;
    int lane = threadIdx.x & 31;
    int t = blockIdx.x * 8 + warp;
    int b = t >> 12;
    int hw = t & 4095;
    int h = hw >> 6, w = hw & 63;
    int hs = (h + 60) & 63;
    int ws = (w + 60) & 63;
    int src = b * 4096 + ((hs >> 3) * 8 + (ws >> 3)) * 64 + ((hs & 7) * 8 + (ws & 7));

    const float* yp = g_bufA + (size_t)src * 256;
    float y[8]; float s = 0.f;
#pragma unroll
    for (int k = 0; k < 8; k++) { y[k] = yp[lane + 32 * k]; s += y[k]; }
#pragma unroll
    for (int o = 16; o > 0; o >>= 1) s += __shfl_xor_sync(0xffffffffu, s, o);
    float mu = s * (1.f / 256.f);
    float vs = 0.f;
#pragma unroll
    for (int k = 0; k < 8; k++) { float d = y[k] - mu; vs += d * d; }
#pragma unroll
    for (int o = 16; o > 0; o >>= 1) vs += __shfl_xor_sync(0xffffffffu, vs, o);
    float rstd = rsqrtf(vs * (1.f / 256.f) + 1e-6f);

    const float* xp = x + (size_t)t * 256;
    float*  op  = g_x1  + (size_t)t * 256;
    __half* oph = g_x1h + (size_t)t * 256;
#pragma unroll
    for (int k = 0; k < 8; k++) {
        int c = lane + 32 * k;
        float v = xp[c] + (y[k] - mu) * rstd * scale[c] + bias[c];
        op[c]  = v;
        oph[c] = __float2half(v);
    }
}

// ---------------- final: out = x1 + LN(fc2_out) ----------------
__global__ void __launch_bounds__(256) final_kernel(float* __restrict__ out,
                                                    const float* __restrict__ scale,
                                                    const float* __restrict__ bias) {
    int warp = threadIdx.x >> 5;
    int lane = threadIdx.x & 31;
    int t = blockIdx.x * 8 + warp;

    const float* yp = g_y2 + (size_t)t * 256;
    float y[8]; float s = 0.f;
#pragma unroll
    for (int k = 0; k < 8; k++) { y[k] = yp[lane + 32 * k]; s += y[k]; }
#pragma unroll
    for (int o = 16; o > 0; o >>= 1) s += __shfl_xor_sync(0xffffffffu, s, o);
    float mu = s * (1.f / 256.f);
    float vs = 0.f;
#pragma unroll
    for (int k = 0; k < 8; k++) { float d = y[k] - mu; vs += d * d; }
#pragma unroll
    for (int o = 16; o > 0; o >>= 1) vs += __shfl_xor_sync(0xffffffffu, vs, o);
    float rstd = rsqrtf(vs * (1.f / 256.f) + 1e-6f);

    const float* x1p = g_x1 + (size_t)t * 256;
    float* op = out + (size_t)t * 256;
#pragma unroll
    for (int k = 0; k < 8; k++) {
        int c = lane + 32 * k;
        op[c] = x1p[c] + (y[k] - mu) * rstd * scale[c] + bias[c];
    }
}

// ---------------- launch ----------------
#define GEMM_SMEM       (65536 + 1024)
#define GEMM_ARES_SMEM  (196608 + 1024)

extern "C" void kernel_launch(void* const* d_in, const int* in_sizes, int n_in,
                              void* d_out, int out_size) {
    const float* x      = (const float*)d_in[0];
    const float* qkv_w  = (const float*)d_in[1];
    const float* q_bias = (const float*)d_in[2];
    const float* v_bias = (const float*)d_in[3];
    const float* lscale = (const float*)d_in[4];
    const float* cpb_w1 = (const float*)d_in[5];
    const float* cpb_b1 = (const float*)d_in[6];
    const float* cpb_w2 = (const float*)d_in[7];
    const float* proj_w = (const float*)d_in[8];
    const float* proj_b = (const float*)d_in[9];
    const float* n1s    = (const float*)d_in[10];
    const float* n1b    = (const float*)d_in[11];
    const float* n2s    = (const float*)d_in[12];
    const float* n2b    = (const float*)d_in[13];
    const float* fc1_w  = (const float*)d_in[14];
    const float* fc1_b  = (const float*)d_in[15];
    const float* fc2_w  = (const float*)d_in[16];
    const float* fc2_b  = (const float*)d_in[17];
    float* out = (float*)d_out;

    float *pA, *pY2, *pB768;
    __half *pXh, *pAh, *pX1h, *pHh, *pWTh, *pQkvh;
    cudaGetSymbolAddress((void**)&pA,    g_bufA);
    cudaGetSymbolAddress((void**)&pY2,   g_y2);
    cudaGetSymbolAddress((void**)&pB768, g_bias768);
    cudaGetSymbolAddress((void**)&pXh,   g_xh);
    cudaGetSymbolAddress((void**)&pAh,   g_ah);
    cudaGetSymbolAddress((void**)&pX1h,  g_x1h);
    cudaGetSymbolAddress((void**)&pHh,   g_hh);
    cudaGetSymbolAddress((void**)&pWTh,  g_wTh);
    cudaGetSymbolAddress((void**)&pQkvh, g_qkvh);

    cudaFuncSetAttribute(gemm_ares<0,0,1>, cudaFuncAttributeMaxDynamicSharedMemorySize, GEMM_ARES_SMEM);
    cudaFuncSetAttribute(gemm_ares<0,1,0>, cudaFuncAttributeMaxDynamicSharedMemorySize, GEMM_ARES_SMEM);
    cudaFuncSetAttribute(gemm_ares<1,0,1>, cudaFuncAttributeMaxDynamicSharedMemorySize, GEMM_ARES_SMEM);
    cudaFuncSetAttribute(gemm_h<0,1,0>,    cudaFuncAttributeMaxDynamicSharedMemorySize, GEMM_SMEM);

    pack_bias_kernel<<<1, 768>>>(q_bias, v_bias);
    cpb_kernel<<<225, 512>>>(cpb_w1, cpb_b1, cpb_w2);
    rpb_kernel<<<dim3(64, 8), 64>>>();

    transpose_kernel<<<dim3(768 / 32, 256 / 32),  dim3(32, 8)>>>(qkv_w,  pWTh + WT_QKV,  256, 768);
    transpose_kernel<<<dim3(256 / 32, 256 / 32),  dim3(32, 8)>>>(proj_w, pWTh + WT_PROJ, 256, 256);
    transpose_kernel<<<dim3(1024 / 32, 256 / 32), dim3(32, 8)>>>(fc1_w,  pWTh + WT_FC1,  256, 1024);
    transpose_kernel<<<dim3(256 / 32, 1024 / 32), dim3(32, 8)>>>(fc2_w,  pWTh + WT_FC2,  1024, 256);

    gather_kernel<<<M_TOK * 64 / 256, 256>>>(x);

    // qkv: (M,256)x(256,768) -> half g_qkvh
    gemm_ares<0,0,1><<<M_TOK / 128, 256, GEMM_ARES_SMEM>>>(
        pXh, pWTh + WT_QKV, pB768, (float*)0, pQkvh, 768);
    attn_kernel<<<2048 * 8, 64>>>(lscale);

    // proj: (M,256)x(256,256) -> fp32 g_bufA
    gemm_ares<0,1,0><<<M_TOK / 128, 256, GEMM_ARES_SMEM>>>(
        pAh, pWTh + WT_PROJ, proj_b, pA, (__half*)0, 256);
    ln1_kernel<<<M_TOK / 8, 256>>>(x, n1s, n1b);

    // fc1+gelu: (M,256)x(256,1024) -> half g_hh
    gemm_ares<1,0,1><<<M_TOK / 128, 256, GEMM_ARES_SMEM>>>(
        pX1h, pWTh + WT_FC1, fc1_b, (float*)0, pHh, 1024);
    // fc2: (M,1024)x(1024,256) -> fp32 g_y2
    gemm_h<0,1,0><<<dim3(2, M_TOK / 128), 256, GEMM_SMEM>>>(
        pHh, pWTh + WT_FC2, fc2_b, pY2, (__half*)0, 256, 1024);
    final_kernel<<<M_TOK / 8, 256>>>(out, n2s, n2b);
}

// round 12
// speedup vs baseline: 3.9448x; 1.0837x over previous
#include <cuda_runtime.h>
#include <cuda_fp16.h>
#include <math.h>
#include <stdint.h>

#define M_TOK 131072          // 32 * 4096 tokens

// ---------------- device scratch ----------------
__device__ float  g_bufA[M_TOK * 256];          // proj output (fp32)
__device__ float  g_y2  [M_TOK * 256];          // fc2 output (fp32)
__device__ float  g_x1  [M_TOK * 256];          // first residual (fp32)
__device__ __half g_qkvh[M_TOK * 768];          // packed qkv (half)
__device__ __half g_xh  [M_TOK * 256];          // gathered x (half)  -> qkv A
__device__ __half g_ah  [M_TOK * 256];          // attn out (half)    -> proj A
__device__ __half g_x1h [M_TOK * 256];          // x1 (half)          -> fc1 A
__device__ __half g_hh  [M_TOK * 1024];         // gelu hidden (half) -> fc2 A
__device__ __half g_wTh [786432];               // transposed weights [N][K] half
__device__ float  g_bias768[768];
__device__ float  g_btab[225 * 8];
__device__ float  g_rpb [8 * 64 * 64];

#define WT_QKV  0
#define WT_PROJ 196608
#define WT_FC1  262144
#define WT_FC2  524288

// ---------------- helpers ----------------
__device__ __forceinline__ uint32_t smem_u32(const void* p) {
    uint32_t a;
    asm("{ .reg .u64 t; cvta.to.shared.u64 t, %1; cvt.u32.u64 %0, t; }"
        : "=r"(a) : "l"(p));
    return a;
}

__device__ __forceinline__ void cp16(uint32_t dst, const void* src) {
    asm volatile("cp.async.cg.shared.global [%0], [%1], 16;" :: "r"(dst), "l"(src) : "memory");
}

__device__ __forceinline__ void ldsm_x4(uint32_t& r0, uint32_t& r1, uint32_t& r2,
                                        uint32_t& r3, uint32_t addr) {
    asm volatile("ldmatrix.sync.aligned.m8n8.x4.shared.b16 {%0,%1,%2,%3}, [%4];"
                 : "=r"(r0), "=r"(r1), "=r"(r2), "=r"(r3) : "r"(addr));
}

__device__ __forceinline__ void mma16816(float& d0, float& d1, float& d2, float& d3,
                                         uint32_t a0, uint32_t a1, uint32_t a2, uint32_t a3,
                                         uint32_t b0, uint32_t b1) {
    asm volatile("mma.sync.aligned.m16n8k16.row.col.f32.f16.f16.f32 "
                 "{%0,%1,%2,%3}, {%4,%5,%6,%7}, {%8,%9}, {%0,%1,%2,%3};"
                 : "+f"(d0), "+f"(d1), "+f"(d2), "+f"(d3)
                 : "r"(a0), "r"(a1), "r"(a2), "r"(a3), "r"(b0), "r"(b1));
}

#define SWZ(x) ((x) ^ (((x) >> 3) & 0x70))

__device__ __forceinline__ float gelu_f(float x) {
    float y = 0.7978845608028654f * (x + 0.044715f * x * x * x);
    float t = 1.f - 2.f / (__expf(2.f * y) + 1.f);
    return 0.5f * x * (1.f + t);
}

// ---------------- tiny precompute kernels ----------------
__global__ void pack_bias_kernel(const float* __restrict__ qb,
                                 const float* __restrict__ vb) {
    int i = threadIdx.x;
    float v = 0.f;
    if (i < 256)       v = qb[i];
    else if (i >= 512) v = vb[i - 512];
    g_bias768[i] = v;
}

__global__ void __launch_bounds__(512) cpb_kernel(const float* __restrict__ w1,
                                                  const float* __restrict__ b1,
                                                  const float* __restrict__ w2) {
    int p = blockIdx.x;
    int i = p / 15, j = p % 15;
    float t0 = (float)(i - 7) * (8.f / 7.f), t1 = (float)(j - 7) * (8.f / 7.f);
    t0 = copysignf(log2f(fabsf(t0) + 1.f) * (1.f / 3.f), t0);
    t1 = copysignf(log2f(fabsf(t1) + 1.f) * (1.f / 3.f), t1);

    int jt = threadIdx.x;
    float hidden = fmaxf(t0 * w1[jt] + t1 * w1[512 + jt] + b1[jt], 0.f);

    __shared__ float sh[512];
    for (int h = 0; h < 8; h++) {
        sh[jt] = hidden * w2[jt * 8 + h];
        __syncthreads();
        for (int off = 256; off > 0; off >>= 1) {
            if (jt < off) sh[jt] += sh[jt + off];
            __syncthreads();
        }
        if (jt == 0) g_btab[p * 8 + h] = sh[0];
        __syncthreads();
    }
}

__global__ void rpb_kernel() {
    int n = blockIdx.x, h = blockIdx.y, m = threadIdx.x;
    int dr = (n >> 3) - (m >> 3) + 7;
    int dc = (n & 7)  - (m & 7)  + 7;
    float v = g_btab[(dr * 15 + dc) * 8 + h];
    g_rpb[h * 4096 + n * 64 + m] = 16.f / (1.f + expf(-v));
}

// src[K][N] fp32 -> dst[N][K] half
__global__ void transpose_kernel(const float* __restrict__ src, __half* __restrict__ dst,
                                 int K, int N) {
    __shared__ float t[32][33];
    int kb = blockIdx.y * 32, nb = blockIdx.x * 32;
#pragma unroll
    for (int i = 0; i < 4; i++)
        t[threadIdx.y + 8 * i][threadIdx.x] =
            src[(size_t)(kb + threadIdx.y + 8 * i) * N + nb + threadIdx.x];
    __syncthreads();
#pragma unroll
    for (int i = 0; i < 4; i++)
        dst[(size_t)(nb + threadIdx.y + 8 * i) * K + kb + threadIdx.x] =
            __float2half(t[threadIdx.x][threadIdx.y + 8 * i]);
}

// ---------------- cyclic shift + window partition gather -> half ----------------
__global__ void gather_kernel(const float* __restrict__ x) {
    int idx = blockIdx.x * 256 + threadIdx.x;
    int row = idx >> 6;
    int qd  = idx & 63;
    int b   = row >> 12;
    int rem = row & 4095;
    int win = rem >> 6;
    int n   = rem & 63;
    int hs  = (win >> 3) * 8 + (n >> 3);
    int ws  = (win & 7)  * 8 + (n & 7);
    int hsrc = (hs + 4) & 63;
    int wsrc = (ws + 4) & 63;
    int src  = b * 4096 + hsrc * 64 + wsrc;
    float4 v = ((const float4*)x)[(size_t)src * 64 + qd];
    __half2 h0 = __float22half2_rn(make_float2(v.x, v.y));
    __half2 h1 = __float22half2_rn(make_float2(v.z, v.w));
    uint2 pk = make_uint2(*(uint32_t*)&h0, *(uint32_t*)&h1);
    ((uint2*)g_xh)[(size_t)row * 64 + qd] = pk;
}

// ================= A-resident FP16 GEMM, 2 CTA/SM (K = 256) =================
// A tile (128x256 half, 64KB, 512B pitch) resident; B staged in 16KB K-chunks
// (128 cols x 64 K, 128B pitch), double-buffered. 96KB total -> 2 CTAs/SM.

__device__ __forceinline__ void stage_tileA(uint32_t dst, const __half* __restrict__ src) {
    int tid = threadIdx.x;
#pragma unroll
    for (int i = 0; i < 16; i++) {
        int id  = tid + 256 * i;
        int row = id >> 5, c = id & 31;
        cp16(dst + row * 512 + ((c ^ (row & 7)) << 4), src + (size_t)row * 256 + c * 8);
    }
}

// stage one 128x64-half B chunk (gmem row-major, ldk=256)
__device__ __forceinline__ void stage_bchunk(uint32_t dst, const __half* __restrict__ src) {
    int tid = threadIdx.x;
#pragma unroll
    for (int i = 0; i < 4; i++) {
        int id  = tid + 256 * i;          // 0..1023
        int row = id >> 3, c = id & 7;
        cp16(dst + row * 128 + ((c ^ (row & 7)) << 4), src + (size_t)row * 256 + c * 8);
    }
}

template <int ACT, int WF, int WH>
__global__ void __launch_bounds__(256, 2) gemm_ares(const __half* __restrict__ A,
                                                    const __half* __restrict__ Bt,
                                                    const float* __restrict__ bias,
                                                    float* __restrict__ Cf,
                                                    __half* __restrict__ Ch,
                                                    int N) {
    extern __shared__ char smem[];
    uint32_t base  = (smem_u32(smem) + 1023u) & ~1023u;
    uint32_t aBuf  = base;
    uint32_t bBuf0 = base + 65536u;
    uint32_t bBuf1 = base + 65536u + 16384u;

    const int tid  = threadIdx.x;
    const int warp = tid >> 5;
    const int lane = tid & 31;
    const int wm   = warp >> 2;
    const int wn   = warp & 3;
    const int row0 = blockIdx.x * 128;
    const int G    = (N >> 7) * 4;        // total 64-K chunks across all N tiles

    // prologue: A + chunk0 in group0, chunk1 in group1
    stage_tileA(aBuf, A + (size_t)row0 * 256);
    stage_bchunk(bBuf0, Bt);                       // g=0: col0=0, kk=0
    asm volatile("cp.async.commit_group;" ::: "memory");
    stage_bchunk(bBuf1, Bt + 64);                  // g=1: col0=0, kk=64
    asm volatile("cp.async.commit_group;" ::: "memory");

    uint32_t a_row[4]; int a_sw[4];
#pragma unroll
    for (int mtl = 0; mtl < 4; mtl++) {
        int r = wm * 64 + mtl * 16 + (lane & 15);
        a_row[mtl] = r * 512;
        a_sw[mtl]  = r & 7;
    }
    const int a_half = lane >> 4;
    uint32_t b_row[2]; int b_sw[2];
    const int gl = lane >> 3;
#pragma unroll
    for (int p = 0; p < 2; p++) {
        int r = wn * 32 + (2 * p + (gl >> 1)) * 8 + (lane & 7);
        b_row[p] = r * 128;
        b_sw[p]  = r & 7;
    }
    const int b_half = gl & 1;

    float acc[4][4][4];

    for (int g = 0; g < G; g++) {
        if (g + 1 < G)
            asm volatile("cp.async.wait_group 1;" ::: "memory");
        else
            asm volatile("cp.async.wait_group 0;" ::: "memory");
        __syncthreads();

        uint32_t bCur = (g & 1) ? bBuf1 : bBuf0;
        const int kc = (g & 3);           // K-chunk within tile
        const int a_co = kc * 8;          // A 16B-chunk offset for this K chunk

        if (kc == 0) {
#pragma unroll
            for (int i = 0; i < 4; i++)
#pragma unroll
                for (int j = 0; j < 4; j++)
#pragma unroll
                    for (int e = 0; e < 4; e++) acc[i][j][e] = 0.f;
        }

#pragma unroll
        for (int ks = 0; ks < 4; ks++) {
            uint32_t af[4][4];
            uint32_t bf[4][2];
#pragma unroll
            for (int mtl = 0; mtl < 4; mtl++) {
                uint32_t addr = aBuf + a_row[mtl] +
                                (uint32_t)(((a_co + ks * 2 + a_half) ^ a_sw[mtl]) << 4);
                ldsm_x4(af[mtl][0], af[mtl][1], af[mtl][2], af[mtl][3], addr);
            }
#pragma unroll
            for (int p = 0; p < 2; p++) {
                uint32_t addr = bCur + b_row[p] +
                                (uint32_t)(((ks * 2 + b_half) ^ b_sw[p]) << 4);
                ldsm_x4(bf[2 * p][0], bf[2 * p][1], bf[2 * p + 1][0], bf[2 * p + 1][1], addr);
            }
#pragma unroll
            for (int mtl = 0; mtl < 4; mtl++)
#pragma unroll
                for (int ntl = 0; ntl < 4; ntl++)
                    mma16816(acc[mtl][ntl][0], acc[mtl][ntl][1],
                             acc[mtl][ntl][2], acc[mtl][ntl][3],
                             af[mtl][0], af[mtl][1], af[mtl][2], af[mtl][3],
                             bf[ntl][0], bf[ntl][1]);
        }
        __syncthreads();   // all warps done reading bCur

        // refill bCur with chunk g+2 (overlaps the epilogue below)
        if (g + 2 < G) {
            int gn = g + 2;
            int col0n = (gn >> 2) << 7;
            int kkn = (gn & 3) * 64;
            stage_bchunk(bCur, Bt + (size_t)col0n * 256 + kkn);
            asm volatile("cp.async.commit_group;" ::: "memory");
        }

        // epilogue at the last chunk of each N tile
        if (kc == 3) {
            int col0 = (g >> 2) << 7;
#pragma unroll
            for (int mtl = 0; mtl < 4; mtl++) {
                int rbase = row0 + wm * 64 + mtl * 16 + (lane >> 2);
#pragma unroll
                for (int ntl = 0; ntl < 4; ntl++) {
                    int cc = col0 + wn * 32 + ntl * 8 + (lane & 3) * 2;
                    float b0 = bias[cc], b1 = bias[cc + 1];
#pragma unroll
                    for (int half = 0; half < 2; half++) {
                        int r = rbase + half * 8;
                        float v0 = acc[mtl][ntl][half * 2 + 0] + b0;
                        float v1 = acc[mtl][ntl][half * 2 + 1] + b1;
                        if (ACT == 1) { v0 = gelu_f(v0); v1 = gelu_f(v1); }
                        if (WF)
                            *(float2*)(Cf + (size_t)r * N + cc) = make_float2(v0, v1);
                        if (WH) {
                            __half2 hv = __float22half2_rn(make_float2(v0, v1));
                            *(uint32_t*)(Ch + (size_t)r * N + cc) = *(uint32_t*)&hv;
                        }
                    }
                }
            }
        }
    }
}

// ================= streamed FP16 GEMM (fc2, K = 1024) =================
template <int ACT, int WF, int WH>
__global__ void __launch_bounds__(256) gemm_h(const __half* __restrict__ A,
                                              const __half* __restrict__ Bt,
                                              const float* __restrict__ bias,
                                              float* __restrict__ Cf,
                                              __half* __restrict__ Ch,
                                              int N, int K) {
    extern __shared__ char smem[];
    uint32_t base = (smem_u32(smem) + 1023u) & ~1023u;
    const int tid  = threadIdx.x;
    const int warp = tid >> 5;
    const int lane = tid & 31;
    const int wm   = warp >> 2;
    const int wn   = warp & 3;
    const int row0 = blockIdx.y * 128;
    const int col0 = blockIdx.x * 128;
    const int chunks = K >> 6;

    const int cp_row = tid >> 3;
    const int cp_c   = tid & 7;

    float acc[4][4][4];
#pragma unroll
    for (int i = 0; i < 4; i++)
#pragma unroll
        for (int j = 0; j < 4; j++)
#pragma unroll
            for (int e = 0; e < 4; e++) acc[i][j][e] = 0.f;

    uint32_t a_base[4], a_x[4];
#pragma unroll
    for (int mtl = 0; mtl < 4; mtl++) {
        int r = wm * 64 + mtl * 16 + (lane & 15);
        a_base[mtl] = r * 128 + ((lane >> 4) * 16);
        a_x[mtl]    = (r & 7) * 16;
    }
    uint32_t b_base[2], b_x;
    {
        int g = lane >> 3;
#pragma unroll
        for (int p = 0; p < 2; p++) {
            int r = wn * 32 + (2 * p + (g >> 1)) * 8 + (lane & 7);
            b_base[p] = r * 128 + ((g & 1) * 16);
        }
        b_x = (lane & 7) * 16;
    }

    {
        uint32_t aB = base, bB = base + 16384u;
#pragma unroll
        for (int i = 0; i < 4; i++) {
            int row = cp_row + i * 32;
            cp16(aB + SWZ(row * 128 + cp_c * 16), A  + (size_t)(row0 + row) * K + cp_c * 8);
            cp16(bB + SWZ(row * 128 + cp_c * 16), Bt + (size_t)(col0 + row) * K + cp_c * 8);
        }
        asm volatile("cp.async.commit_group;" ::: "memory");
    }

    for (int c = 0; c < chunks; c++) {
        if (c + 1 < chunks) {
            uint32_t st = ((c + 1) & 1) * 32768u;
            uint32_t aB = base + st, bB = base + 16384u + st;
            int kk = (c + 1) * 64;
#pragma unroll
            for (int i = 0; i < 4; i++) {
                int row = cp_row + i * 32;
                cp16(aB + SWZ(row * 128 + cp_c * 16),
                     A  + (size_t)(row0 + row) * K + kk + cp_c * 8);
                cp16(bB + SWZ(row * 128 + cp_c * 16),
                     Bt + (size_t)(col0 + row) * K + kk + cp_c * 8);
            }
            asm volatile("cp.async.commit_group;" ::: "memory");
            asm volatile("cp.async.wait_group 1;" ::: "memory");
        } else {
            asm volatile("cp.async.wait_group 0;" ::: "memory");
        }
        __syncthreads();

        uint32_t st = (c & 1) * 32768u;
        uint32_t aCur = base + st, bCur = base + 16384u + st;
#pragma unroll
        for (int ks = 0; ks < 4; ks++) {
            uint32_t ko = ks << 5;
            uint32_t af[4][4];
            uint32_t bf[4][2];
#pragma unroll
            for (int mtl = 0; mtl < 4; mtl++)
                ldsm_x4(af[mtl][0], af[mtl][1], af[mtl][2], af[mtl][3],
                        aCur + ((a_base[mtl] + ko) ^ a_x[mtl]));
#pragma unroll
            for (int p = 0; p < 2; p++)
                ldsm_x4(bf[2 * p][0], bf[2 * p][1], bf[2 * p + 1][0], bf[2 * p + 1][1],
                        bCur + ((b_base[p] + ko) ^ b_x));
#pragma unroll
            for (int mtl = 0; mtl < 4; mtl++)
#pragma unroll
                for (int ntl = 0; ntl < 4; ntl++)
                    mma16816(acc[mtl][ntl][0], acc[mtl][ntl][1],
                             acc[mtl][ntl][2], acc[mtl][ntl][3],
                             af[mtl][0], af[mtl][1], af[mtl][2], af[mtl][3],
                             bf[ntl][0], bf[ntl][1]);
        }
        __syncthreads();
    }

#pragma unroll
    for (int mtl = 0; mtl < 4; mtl++) {
        int rbase = row0 + wm * 64 + mtl * 16 + (lane >> 2);
#pragma unroll
        for (int ntl = 0; ntl < 4; ntl++) {
            int cc = col0 + wn * 32 + ntl * 8 + (lane & 3) * 2;
            float b0 = bias[cc], b1 = bias[cc + 1];
#pragma unroll
            for (int half = 0; half < 2; half++) {
                int r = rbase + half * 8;
                float v0 = acc[mtl][ntl][half * 2 + 0] + b0;
                float v1 = acc[mtl][ntl][half * 2 + 1] + b1;
                if (ACT == 1) { v0 = gelu_f(v0); v1 = gelu_f(v1); }
                if (WF)
                    *(float2*)(Cf + (size_t)r * N + cc) = make_float2(v0, v1);
                if (WH) {
                    __half2 hv = __float22half2_rn(make_float2(v0, v1));
                    *(uint32_t*)(Ch + (size_t)r * N + cc) = *(uint32_t*)&hv;
                }
            }
        }
    }
}

// ---------------- window attention (qkv in half) ----------------
__device__ __forceinline__ void load_row32(const __half* p, float* out) {
    const uint4* q = (const uint4*)p;
#pragma unroll
    for (int i = 0; i < 4; i++) {
        uint4 u = q[i];
        float2 f0 = __half22float2(*(__half2*)&u.x);
        float2 f1 = __half22float2(*(__half2*)&u.y);
        float2 f2 = __half22float2(*(__half2*)&u.z);
        float2 f3 = __half22float2(*(__half2*)&u.w);
        out[i * 8 + 0] = f0.x; out[i * 8 + 1] = f0.y;
        out[i * 8 + 2] = f1.x; out[i * 8 + 3] = f1.y;
        out[i * 8 + 4] = f2.x; out[i * 8 + 5] = f2.y;
        out[i * 8 + 6] = f3.x; out[i * 8 + 7] = f3.y;
    }
}

__global__ void __launch_bounds__(64) attn_kernel(const float* __restrict__ logit_scale) {
    int bi = blockIdx.x;
    int b_ = bi >> 3;
    int hh = bi & 7;
    int n  = threadIdx.x;
    int win = b_ & 63;
    int wh = win >> 3, ww = win & 7;

    __shared__ float4 sk4[64][8];
    __shared__ float4 sv4[64][8];
    __shared__ int    sreg[64];

    const __half* base = g_qkvh + (size_t)(b_ * 64) * 768;

    float q[32], kr[32], vr[32];
    load_row32(base + (size_t)n * 768 + hh * 32, q);
    load_row32(base + (size_t)n * 768 + 256 + hh * 32, kr);
    load_row32(base + (size_t)n * 768 + 512 + hh * 32, vr);

    {
        float ss = 0.f;
#pragma unroll
        for (int d = 0; d < 32; d++) ss += q[d] * q[d];
        float rn = rsqrtf(fmaxf(ss, 1e-12f));
#pragma unroll
        for (int d = 0; d < 32; d++) q[d] *= rn;
    }
    {
        float ks = 0.f;
#pragma unroll
        for (int d = 0; d < 32; d++) ks += kr[d] * kr[d];
        float rk = rsqrtf(fmaxf(ks, 1e-12f));
#pragma unroll
        for (int j = 0; j < 8; j++)
            sk4[n][j] = make_float4(kr[4*j] * rk, kr[4*j+1] * rk,
                                    kr[4*j+2] * rk, kr[4*j+3] * rk);
    }
#pragma unroll
    for (int j = 0; j < 8; j++)
        sv4[n][j] = make_float4(vr[4*j], vr[4*j+1], vr[4*j+2], vr[4*j+3]);
    {
        int r = n >> 3, c = n & 7;
        int habs = wh * 8 + r, wabs = ww * 8 + c;
        int rh = habs < 56 ? 0 : (habs < 60 ? 1 : 2);
        int rw = wabs < 56 ? 0 : (wabs < 60 ? 1 : 2);
        sreg[n] = rh * 3 + rw;
    }
    __syncthreads();

    float scale = __expf(fminf(logit_scale[hh], 4.605170185988092f));
    int myreg = sreg[n];
    const float* rpb = g_rpb + hh * 4096 + n * 64;

    float a[64];
    float amax = -1e30f;
#pragma unroll
    for (int m = 0; m < 64; m++) {
        float dot = 0.f;
#pragma unroll
        for (int j = 0; j < 8; j++) {
            float4 kk = sk4[m][j];
            dot += q[4*j] * kk.x + q[4*j+1] * kk.y + q[4*j+2] * kk.z + q[4*j+3] * kk.w;
        }
        float v = dot * scale + rpb[m];
        if (sreg[m] != myreg) v -= 100.f;
        a[m] = v;
        amax = fmaxf(amax, v);
    }
    float asum = 0.f;
#pragma unroll
    for (int m = 0; m < 64; m++) { a[m] = __expf(a[m] - amax); asum += a[m]; }
    float inv = 1.f / asum;

    float4 o[8];
#pragma unroll
    for (int j = 0; j < 8; j++) o[j] = make_float4(0.f, 0.f, 0.f, 0.f);
#pragma unroll
    for (int m = 0; m < 64; m++) {
        float am = a[m] * inv;
#pragma unroll
        for (int j = 0; j < 8; j++) {
            float4 vv = sv4[m][j];
            o[j].x += am * vv.x; o[j].y += am * vv.y;
            o[j].z += am * vv.z; o[j].w += am * vv.w;
        }
    }
    uint2* op = (uint2*)(g_ah + (size_t)(b_ * 64 + n) * 256 + hh * 32);
#pragma unroll
    for (int j = 0; j < 8; j++) {
        __half2 h0 = __float22half2_rn(make_float2(o[j].x, o[j].y));
        __half2 h1 = __float22half2_rn(make_float2(o[j].z, o[j].w));
        op[j] = make_uint2(*(uint32_t*)&h0, *(uint32_t*)&h1);
    }
}

// ---------------- LN + residual (branch 1) ----------------
__global__ void __launch_bounds__(256) ln1_kernel(const float* __restrict__ x,
                                                  const float* __restrict__ scale,
                                                  const float* __restrict__ bias) {
    int warp = threadIdx.x >> 5;
    int lane = threadIdx.x & 31;
    int t = blockIdx.x * 8 + warp;
    int b = t >> 12;
    int hw = t & 4095;
    int h = hw >> 6, w = hw & 63;
    int hs = (h + 60) & 63;
    int ws = (w + 60) & 63;
    int src = b * 4096 + ((hs >> 3) * 8 + (ws >> 3)) * 64 + ((hs & 7) * 8 + (ws & 7));

    const float* yp = g_bufA + (size_t)src * 256;
    float y[8]; float s = 0.f;
#pragma unroll
    for (int k = 0; k < 8; k++) { y[k] = yp[lane + 32 * k]; s += y[k]; }
#pragma unroll
    for (int o = 16; o > 0; o >>= 1) s += __shfl_xor_sync(0xffffffffu, s, o);
    float mu = s * (1.f / 256.f);
    float vs = 0.f;
#pragma unroll
    for (int k = 0; k < 8; k++) { float d = y[k] - mu; vs += d * d; }
#pragma unroll
    for (int o = 16; o > 0; o >>= 1) vs += __shfl_xor_sync(0xffffffffu, vs, o);
    float rstd = rsqrtf(vs * (1.f / 256.f) + 1e-6f);

    const float* xp = x + (size_t)t * 256;
    float*  op  = g_x1  + (size_t)t * 256;
    __half* oph = g_x1h + (size_t)t * 256;
#pragma unroll
    for (int k = 0; k < 8; k++) {
        int c = lane + 32 * k;
        float v = xp[c] + (y[k] - mu) * rstd * scale[c] + bias[c];
        op[c]  = v;
        oph[c] = __float2half(v);
    }
}

// ---------------- final: out = x1 + LN(fc2_out) ----------------
__global__ void __launch_bounds__(256) final_kernel(float* __restrict__ out,
                                                    const float* __restrict__ scale,
                                                    const float* __restrict__ bias) {
    int warp = threadIdx.x >> 5;
    int lane = threadIdx.x & 31;
    int t = blockIdx.x * 8 + warp;

    const float* yp = g_y2 + (size_t)t * 256;
    float y[8]; float s = 0.f;
#pragma unroll
    for (int k = 0; k < 8; k++) { y[k] = yp[lane + 32 * k]; s += y[k]; }
#pragma unroll
    for (int o = 16; o > 0; o >>= 1) s += __shfl_xor_sync(0xffffffffu, s, o);
    float mu = s * (1.f / 256.f);
    float vs = 0.f;
#pragma unroll
    for (int k = 0; k < 8; k++) { float d = y[k] - mu; vs += d * d; }
#pragma unroll
    for (int o = 16; o > 0; o >>= 1) vs += __shfl_xor_sync(0xffffffffu, vs, o);
    float rstd = rsqrtf(vs * (1.f / 256.f) + 1e-6f);

    const float* x1p = g_x1 + (size_t)t * 256;
    float* op = out + (size_t)t * 256;
#pragma unroll
    for (int k = 0; k < 8; k++) {
        int c = lane + 32 * k;
        op[c] = x1p[c] + (y[k] - mu) * rstd * scale[c] + bias[c];
    }
}

// ---------------- launch ----------------
#define GEMM_SMEM       (65536 + 1024)
#define GEMM_ARES_SMEM  (98304 + 1024)

extern "C" void kernel_launch(void* const* d_in, const int* in_sizes, int n_in,
                              void* d_out, int out_size) {
    const float* x      = (const float*)d_in[0];
    const float* qkv_w  = (const float*)d_in[1];
    const float* q_bias = (const float*)d_in[2];
    const float* v_bias = (const float*)d_in[3];
    const float* lscale = (const float*)d_in[4];
    const float* cpb_w1 = (const float*)d_in[5];
    const float* cpb_b1 = (const float*)d_in[6];
    const float* cpb_w2 = (const float*)d_in[7];
    const float* proj_w = (const float*)d_in[8];
    const float* proj_b = (const float*)d_in[9];
    const float* n1s    = (const float*)d_in[10];
    const float* n1b    = (const float*)d_in[11];
    const float* n2s    = (const float*)d_in[12];
    const float* n2b    = (const float*)d_in[13];
    const float* fc1_w  = (const float*)d_in[14];
    const float* fc1_b  = (const float*)d_in[15];
    const float* fc2_w  = (const float*)d_in[16];
    const float* fc2_b  = (const float*)d_in[17];
    float* out = (float*)d_out;

    float *pA, *pY2, *pB768;
    __half *pXh, *pAh, *pX1h, *pHh, *pWTh, *pQkvh;
    cudaGetSymbolAddress((void**)&pA,    g_bufA);
    cudaGetSymbolAddress((void**)&pY2,   g_y2);
    cudaGetSymbolAddress((void**)&pB768, g_bias768);
    cudaGetSymbolAddress((void**)&pXh,   g_xh);
    cudaGetSymbolAddress((void**)&pAh,   g_ah);
    cudaGetSymbolAddress((void**)&pX1h,  g_x1h);
    cudaGetSymbolAddress((void**)&pHh,   g_hh);
    cudaGetSymbolAddress((void**)&pWTh,  g_wTh);
    cudaGetSymbolAddress((void**)&pQkvh, g_qkvh);

    cudaFuncSetAttribute(gemm_ares<0,0,1>, cudaFuncAttributeMaxDynamicSharedMemorySize, GEMM_ARES_SMEM);
    cudaFuncSetAttribute(gemm_ares<0,1,0>, cudaFuncAttributeMaxDynamicSharedMemorySize, GEMM_ARES_SMEM);
    cudaFuncSetAttribute(gemm_ares<1,0,1>, cudaFuncAttributeMaxDynamicSharedMemorySize, GEMM_ARES_SMEM);
    cudaFuncSetAttribute(gemm_h<0,1,0>,    cudaFuncAttributeMaxDynamicSharedMemorySize, GEMM_SMEM);

    pack_bias_kernel<<<1, 768>>>(q_bias, v_bias);
    cpb_kernel<<<225, 512>>>(cpb_w1, cpb_b1, cpb_w2);
    rpb_kernel<<<dim3(64, 8), 64>>>();

    transpose_kernel<<<dim3(768 / 32, 256 / 32),  dim3(32, 8)>>>(qkv_w,  pWTh + WT_QKV,  256, 768);
    transpose_kernel<<<dim3(256 / 32, 256 / 32),  dim3(32, 8)>>>(proj_w, pWTh + WT_PROJ, 256, 256);
    transpose_kernel<<<dim3(1024 / 32, 256 / 32), dim3(32, 8)>>>(fc1_w,  pWTh + WT_FC1,  256, 1024);
    transpose_kernel<<<dim3(256 / 32, 1024 / 32), dim3(32, 8)>>>(fc2_w,  pWTh + WT_FC2,  1024, 256);

    gather_kernel<<<M_TOK * 64 / 256, 256>>>(x);

    // qkv: (M,256)x(256,768) -> half g_qkvh
    gemm_ares<0,0,1><<<M_TOK / 128, 256, GEMM_ARES_SMEM>>>(
        pXh, pWTh + WT_QKV, pB768, (float*)0, pQkvh, 768);
    attn_kernel<<<2048 * 8, 64>>>(lscale);

    // proj: (M,256)x(256,256) -> fp32 g_bufA
    gemm_ares<0,1,0><<<M_TOK / 128, 256, GEMM_ARES_SMEM>>>(
        pAh, pWTh + WT_PROJ, proj_b, pA, (__half*)0, 256);
    ln1_kernel<<<M_TOK / 8, 256>>>(x, n1s, n1b);

    // fc1+gelu: (M,256)x(256,1024) -> half g_hh
    gemm_ares<1,0,1><<<M_TOK / 128, 256, GEMM_ARES_SMEM>>>(
        pX1h, pWTh + WT_FC1, fc1_b, (float*)0, pHh, 1024);
    // fc2: (M,1024)x(1024,256) -> fp32 g_y2
    gemm_h<0,1,0><<<dim3(2, M_TOK / 128), 256, GEMM_SMEM>>>(
        pHh, pWTh + WT_FC2, fc2_b, pY2, (__half*)0, 256, 1024);
    final_kernel<<<M_TOK / 8, 256>>>(out, n2s, n2b);
}